// round 11
// baseline (speedup 1.0000x reference)
#include <cuda_runtime.h>
#include <cuda_bf16.h>
#include <math.h>
#include <stdint.h>

// Problem dims (fixed)
#define BBATCH 2
#define LL   1024
#define HH   2048
#define DD   4096      // d = H*E
#define SSTATE 16
#define RR   128
#define TT   2048      // B*L tokens
#define XDBL_N 160     // R + 2S
#define XPAD 256       // padded x_dbl width
#define NSPLITK 8

// ---------------- scratch (static device globals; no allocation) ----------
__device__ float g_xz  [(size_t)TT * 2 * DD];
__device__ float g_xc  [(size_t)TT * DD];
__device__ float g_xdbl[(size_t)TT * XPAD];                 // padded
__device__ float g_xpart[(size_t)NSPLITK * TT * XPAD];      // split-K partials
__device__ float g_dt  [(size_t)TT * DD];

// bf16 split operands (hi/lo)
__device__ __nv_bfloat16 g_xh [(size_t)TT * HH];
__device__ __nv_bfloat16 g_xl [(size_t)TT * HH];
__device__ __nv_bfloat16 g_wih[(size_t)2 * DD * HH];   // W_in^T  [8192][2048]
__device__ __nv_bfloat16 g_wil[(size_t)2 * DD * HH];
__device__ __nv_bfloat16 g_woh[(size_t)HH * DD];       // W_out^T [2048][4096]
__device__ __nv_bfloat16 g_wol[(size_t)HH * DD];
__device__ __nv_bfloat16 g_wdh[(size_t)DD * RR];       // W_dt^T  [4096][128]
__device__ __nv_bfloat16 g_wdl[(size_t)DD * RR];
__device__ __nv_bfloat16 g_wxh[(size_t)XPAD * DD];     // W_x^T   [256(pad)][4096], rows 160+ stay 0
__device__ __nv_bfloat16 g_wxl[(size_t)XPAD * DD];
__device__ __nv_bfloat16 g_xch[(size_t)TT * DD];       // split of xc
__device__ __nv_bfloat16 g_xcl[(size_t)TT * DD];
__device__ __nv_bfloat16 g_dih[(size_t)TT * RR];       // dt_in   [2048][128]
__device__ __nv_bfloat16 g_dil[(size_t)TT * RR];
__device__ __nv_bfloat16 g_yh [(size_t)TT * DD];
__device__ __nv_bfloat16 g_yl [(size_t)TT * DD];

// ---------------- small helpers ------------------------------------------
__device__ __forceinline__ float silu_f(float x) { return x / (1.0f + __expf(-x)); }
__device__ __forceinline__ float softplus_f(float x) {
    return fmaxf(x, 0.0f) + log1pf(__expf(-fabsf(x)));
}
__device__ __forceinline__ uint32_t smem_u32(const void* p) {
    uint32_t a;
    asm("{ .reg .u64 t; cvta.to.shared.u64 t, %1; cvt.u32.u64 %0, t; }" : "=r"(a) : "l"(p));
    return a;
}
__device__ __forceinline__ unsigned short bf16_bits(__nv_bfloat16 h) {
    unsigned short u; *(__nv_bfloat16*)&u = h; return u;
}
__device__ __forceinline__ void split1(float v, unsigned short& h, unsigned short& l) {
    __nv_bfloat16 hb = __float2bfloat16(v);
    __nv_bfloat16 lb = __float2bfloat16(v - __bfloat162float(hb));
    h = bf16_bits(hb); l = bf16_bits(lb);
}
__device__ __forceinline__ void cp_async16(uint32_t dst, const void* src) {
    asm volatile("cp.async.cg.shared.global [%0], [%1], 16;" :: "r"(dst), "l"(src));
}
__device__ __forceinline__ void ldsm_x4(uint32_t addr, uint32_t& r0, uint32_t& r1,
                                        uint32_t& r2, uint32_t& r3) {
    asm volatile("ldmatrix.sync.aligned.m8n8.x4.shared.b16 {%0,%1,%2,%3}, [%4];"
                 : "=r"(r0), "=r"(r1), "=r"(r2), "=r"(r3) : "r"(addr));
}
__device__ __forceinline__ void mma_bf16(float* c, const uint32_t* a,
                                         uint32_t b0, uint32_t b1) {
    asm volatile(
        "mma.sync.aligned.m16n8k16.row.col.f32.bf16.bf16.f32 "
        "{%0,%1,%2,%3}, {%4,%5,%6,%7}, {%8,%9}, {%0,%1,%2,%3};"
        : "+f"(c[0]), "+f"(c[1]), "+f"(c[2]), "+f"(c[3])
        : "r"(a[0]), "r"(a[1]), "r"(a[2]), "r"(a[3]), "r"(b0), "r"(b1));
}

// ---------------- mma.sync split-bf16 GEMM, 256x128 tile ------------------
#define G_AT 32768                   // A tile bytes: 256 x 128B
#define G_BT 16384                   // B tile bytes: 128 x 128B
#define G_STAGE (2*G_AT + 2*G_BT)    // 96KB
#define G_SMEM (2*G_STAGE + 1024)

template<int EPI>
__global__ __launch_bounds__(256, 1)
void mma_gemm256(const __nv_bfloat16* __restrict__ Ah, const __nv_bfloat16* __restrict__ Al,
                 const __nv_bfloat16* __restrict__ Bh, const __nv_bfloat16* __restrict__ Bl,
                 float* __restrict__ C, int M, int N, int ldk,
                 int kLen, const float* __restrict__ bias)
{
    extern __shared__ char smem_raw[];
    const uint32_t sb = (smem_u32(smem_raw) + 1023u) & ~1023u;

    const int tid  = threadIdx.x;
    const int lane = tid & 31;
    const int wid  = tid >> 5;
    const int wm   = wid & 3;
    const int wn   = wid >> 2;
    const int bm = blockIdx.y * 256;
    const int bn = blockIdx.x * 128;
    const int kOff = blockIdx.z * kLen;
    C += (size_t)blockIdx.z * (size_t)M * (size_t)N;   // split-K partial plane

    uint32_t swA[8]; size_t gA[8];
    #pragma unroll
    for (int i = 0; i < 8; i++) {
        int c = i * 256 + tid;
        int row = c >> 3, kb = c & 7;
        uint32_t o = (uint32_t)(row * 128 + kb * 16);
        swA[i] = o ^ ((o >> 3) & 0x70);
        gA[i]  = (size_t)row * (size_t)ldk * 2 + (size_t)kb * 16;
    }
    uint32_t swB[4]; size_t gB[4];
    #pragma unroll
    for (int i = 0; i < 4; i++) {
        int c = i * 256 + tid;
        int row = c >> 3, kb = c & 7;
        uint32_t o = (uint32_t)(row * 128 + kb * 16);
        swB[i] = o ^ ((o >> 3) & 0x70);
        gB[i]  = (size_t)row * (size_t)ldk * 2 + (size_t)kb * 16;
    }
    const char* srcAh = (const char*)(Ah + (size_t)bm * ldk + kOff);
    const char* srcAl = (const char*)(Al + (size_t)bm * ldk + kOff);
    const char* srcBh = (const char*)(Bh + (size_t)bn * ldk + kOff);
    const char* srcBl = (const char*)(Bl + (size_t)bn * ldk + kOff);

    float acc[4][8][4];
    #pragma unroll
    for (int mi = 0; mi < 4; mi++)
        #pragma unroll
        for (int ni = 0; ni < 8; ni++)
            #pragma unroll
            for (int r = 0; r < 4; r++) acc[mi][ni][r] = 0.0f;

    const int NK = kLen >> 6;

    auto load_stage = [&](int kblk, int s) {
        uint32_t base = sb + (uint32_t)s * G_STAGE;
        size_t kadd = (size_t)kblk * 128;
        #pragma unroll
        for (int i = 0; i < 8; i++) cp_async16(base + swA[i],           srcAh + kadd + gA[i]);
        #pragma unroll
        for (int i = 0; i < 8; i++) cp_async16(base + G_AT + swA[i],    srcAl + kadd + gA[i]);
        #pragma unroll
        for (int i = 0; i < 4; i++) cp_async16(base + 2*G_AT + swB[i],  srcBh + kadd + gB[i]);
        #pragma unroll
        for (int i = 0; i < 4; i++) cp_async16(base + 2*G_AT + G_BT + swB[i], srcBl + kadd + gB[i]);
        asm volatile("cp.async.commit_group;" ::: "memory");
    };

    load_stage(0, 0);

    for (int kblk = 0; kblk < NK; kblk++) {
        int s = kblk & 1;
        if (kblk + 1 < NK) {
            load_stage(kblk + 1, 1 - s);
            asm volatile("cp.async.wait_group 1;" ::: "memory");
        } else {
            asm volatile("cp.async.wait_group 0;" ::: "memory");
        }
        __syncthreads();

        uint32_t base = sb + (uint32_t)s * G_STAGE;
        uint32_t tAh = base, tAl = base + G_AT;
        uint32_t tBh = base + 2*G_AT, tBl = base + 2*G_AT + G_BT;

        #pragma unroll
        for (int kk = 0; kk < 4; kk++) {
            const int kb = kk * 32;
            uint32_t aoff[4], boff[4];
            #pragma unroll
            for (int mi = 0; mi < 4; mi++) {
                int mrow = wm * 64 + mi * 16 + (lane & 15);
                int ko   = kb + ((lane >> 4) << 4);
                uint32_t o = (uint32_t)(mrow * 128 + ko);
                aoff[mi] = o ^ ((o >> 3) & 0x70);
            }
            #pragma unroll
            for (int nj = 0; nj < 4; nj++) {
                int nrow = wn * 64 + nj * 16 + (lane & 7) + ((lane >> 4) << 3);
                int ko   = kb + (((lane >> 3) & 1) << 4);
                uint32_t o = (uint32_t)(nrow * 128 + ko);
                boff[nj] = o ^ ((o >> 3) & 0x70);
            }

            uint32_t ah[16], bb[16], tt[16];
            #pragma unroll
            for (int mi = 0; mi < 4; mi++)
                ldsm_x4(tAh + aoff[mi], ah[mi*4+0], ah[mi*4+1], ah[mi*4+2], ah[mi*4+3]);
            #pragma unroll
            for (int nj = 0; nj < 4; nj++)
                ldsm_x4(tBh + boff[nj], bb[nj*4+0], bb[nj*4+1], bb[nj*4+2], bb[nj*4+3]);
            // pass 0: ah * bh
            #pragma unroll
            for (int mi = 0; mi < 4; mi++)
                #pragma unroll
                for (int ni = 0; ni < 8; ni++)
                    mma_bf16(acc[mi][ni], &ah[mi*4], bb[ni*2], bb[ni*2+1]);
            // pass 1: al * bh
            #pragma unroll
            for (int mi = 0; mi < 4; mi++)
                ldsm_x4(tAl + aoff[mi], tt[mi*4+0], tt[mi*4+1], tt[mi*4+2], tt[mi*4+3]);
            #pragma unroll
            for (int mi = 0; mi < 4; mi++)
                #pragma unroll
                for (int ni = 0; ni < 8; ni++)
                    mma_bf16(acc[mi][ni], &tt[mi*4], bb[ni*2], bb[ni*2+1]);
            // pass 2: ah * bl
            #pragma unroll
            for (int nj = 0; nj < 4; nj++)
                ldsm_x4(tBl + boff[nj], tt[nj*4+0], tt[nj*4+1], tt[nj*4+2], tt[nj*4+3]);
            #pragma unroll
            for (int mi = 0; mi < 4; mi++)
                #pragma unroll
                for (int ni = 0; ni < 8; ni++)
                    mma_bf16(acc[mi][ni], &ah[mi*4], tt[ni*2], tt[ni*2+1]);
        }
        __syncthreads();
    }

    #pragma unroll
    for (int mi = 0; mi < 4; mi++) {
        #pragma unroll
        for (int ni = 0; ni < 8; ni++) {
            int row = bm + wm * 64 + mi * 16 + (lane >> 2);
            int col = bn + wn * 64 + ni * 8 + (lane & 3) * 2;
            float2 v0 = make_float2(acc[mi][ni][0], acc[mi][ni][1]);
            float2 v1 = make_float2(acc[mi][ni][2], acc[mi][ni][3]);
            if (EPI == 1) {
                float b0 = __ldg(bias + col), b1 = __ldg(bias + col + 1);
                v0.x = softplus_f(v0.x + b0); v0.y = softplus_f(v0.y + b1);
                v1.x = softplus_f(v1.x + b0); v1.y = softplus_f(v1.y + b1);
            }
            *(float2*)(C + (size_t)row * N + col)       = v0;
            *(float2*)(C + (size_t)(row + 8) * N + col) = v1;
        }
    }
}

// ---------------- prep kernels --------------------------------------------
__global__ __launch_bounds__(256)
void split_kernel(const float* __restrict__ in, __nv_bfloat16* __restrict__ hi,
                  __nv_bfloat16* __restrict__ lo, int n4)
{
    int i = blockIdx.x * 256 + threadIdx.x;
    if (i >= n4) return;
    float4 v = ((const float4*)in)[i];
    ushort4 h, l;
    split1(v.x, h.x, l.x); split1(v.y, h.y, l.y);
    split1(v.z, h.z, l.z); split1(v.w, h.w, l.w);
    ((ushort4*)hi)[i] = h;
    ((ushort4*)lo)[i] = l;
}

// in: [R][C] fp32 -> outH/L: [C][R] bf16  (R, C multiples of 32)
__global__ __launch_bounds__(256)
void trsplit_kernel(const float* __restrict__ in, __nv_bfloat16* __restrict__ oh,
                    __nv_bfloat16* __restrict__ ol, int R, int C)
{
    __shared__ float t[32][33];
    int c0 = blockIdx.x * 32, r0 = blockIdx.y * 32;
    int tx = threadIdx.x, ty = threadIdx.y;
    #pragma unroll
    for (int j = 0; j < 4; j++)
        t[ty + 8 * j][tx] = in[(size_t)(r0 + ty + 8 * j) * C + c0 + tx];
    __syncthreads();
    #pragma unroll
    for (int j = 0; j < 4; j++) {
        float v = t[tx][ty + 8 * j];
        unsigned short h, l; split1(v, h, l);
        size_t o = (size_t)(c0 + ty + 8 * j) * R + r0 + tx;
        *(unsigned short*)(oh + o) = h;
        *(unsigned short*)(ol + o) = l;
    }
}

// reduce split-K partials -> xdbl (padded) + fused dt_in bf16 split
__global__ __launch_bounds__(256)
void xdbl_reduce_kernel(const float* __restrict__ part, float* __restrict__ xdbl,
                        __nv_bfloat16* __restrict__ dih, __nv_bfloat16* __restrict__ dil)
{
    int i = blockIdx.x * 256 + threadIdx.x;
    if (i >= TT * (XPAD / 4)) return;
    float4 s = make_float4(0.f, 0.f, 0.f, 0.f);
    #pragma unroll
    for (int z = 0; z < NSPLITK; z++) {
        float4 v = ((const float4*)(part + (size_t)z * TT * XPAD))[i];
        s.x += v.x; s.y += v.y; s.z += v.z; s.w += v.w;
    }
    ((float4*)xdbl)[i] = s;
    int col = (i & (XPAD/4 - 1)) * 4;
    if (col < RR) {
        int row = i / (XPAD/4);
        ushort4 h, l;
        split1(s.x, h.x, l.x); split1(s.y, h.y, l.y);
        split1(s.z, h.z, l.z); split1(s.w, h.w, l.w);
        size_t o = ((size_t)row * RR + col) >> 2;
        ((ushort4*)dih)[o] = h;
        ((ushort4*)dil)[o] = l;
    }
}

// ---------------- depthwise conv3 + bias + SiLU (+ bf16 split out) --------
__global__ __launch_bounds__(256)
void conv_silu_kernel(const float* __restrict__ xz, const float* __restrict__ w,
                      const float* __restrict__ bias, float* __restrict__ xc,
                      __nv_bfloat16* __restrict__ xch, __nv_bfloat16* __restrict__ xcl)
{
    int i = blockIdx.x * blockDim.x + threadIdx.x;
    const int NW = TT * (DD/4);
    if (i >= NW) return;
    int c4 = i % (DD/4);
    int t  = i / (DD/4);
    int l  = t & (LL - 1);
    int c  = c4 * 4;

    const float* p = xz + (size_t)t * (2*DD) + c;
    float4 x0 = *(const float4*)p;
    float4 xm = (l > 0)      ? *(const float4*)(p - 2*DD) : make_float4(0,0,0,0);
    float4 xp = (l < LL - 1) ? *(const float4*)(p + 2*DD) : make_float4(0,0,0,0);

    float xmv[4] = {xm.x, xm.y, xm.z, xm.w};
    float x0v[4] = {x0.x, x0.y, x0.z, x0.w};
    float xpv[4] = {xp.x, xp.y, xp.z, xp.w};
    float out[4];
    #pragma unroll
    for (int j = 0; j < 4; j++) {
        int cc = c + j;
        float v = xmv[j]*w[cc*3+0] + x0v[j]*w[cc*3+1] + xpv[j]*w[cc*3+2] + bias[cc];
        out[j] = silu_f(v);
    }
    *(float4*)(xc + (size_t)t*DD + c) = make_float4(out[0], out[1], out[2], out[3]);
    ushort4 h, l4;
    split1(out[0], h.x, l4.x); split1(out[1], h.y, l4.y);
    split1(out[2], h.z, l4.z); split1(out[3], h.w, l4.w);
    size_t o = ((size_t)t*DD + c) >> 2;
    ((ushort4*)xch)[o] = h;
    ((ushort4*)xcl)[o] = l4;
}

// ---------------- selective scan + fused gated mix ------------------------
// B/C staged in smem per 64-step chunk (cp.async double buffer); output is
// the gated-mixed y split to bf16 hi/lo (feeds out-GEMM directly).
#define SCH 64
__global__ __launch_bounds__(128)
void scan_kernel(const float* __restrict__ xc, const float* __restrict__ dt,
                 const float* __restrict__ xdbl, const float* __restrict__ A_log,
                 const float* __restrict__ xz, const float* __restrict__ Dp,
                 __nv_bfloat16* __restrict__ yh, __nv_bfloat16* __restrict__ yl)
{
    __shared__ float4 sBC[2][SCH][8];
    const int tid = threadIdx.x;
    const int c = blockIdx.x * 128 + tid;
    const int b = blockIdx.y;

    float eps[SSTATE];
    #pragma unroll
    for (int s = 0; s < SSTATE; s++)
        eps[s] = (float)(s + 1) - expf(A_log[(size_t)c*SSTATE + s]);
    const float Dv = Dp[c];

    float h[SSTATE];
    #pragma unroll
    for (int s = 0; s < SSTATE; s++) h[s] = 0.0f;

    const size_t base  = (size_t)b * LL * DD + c;
    const size_t zbase = (size_t)b * LL * (2*DD) + DD + c;
    const float* xrow  = xdbl + (size_t)b * LL * XPAD + RR;

    const uint32_t sbase = smem_u32(&sBC[0][0][0]);
    auto load_chunk = [&](int lc, int buf) {
        #pragma unroll
        for (int k = 0; k < 4; k++) {
            int idx = k * 128 + tid;           // 0..511
            int r = idx >> 3, q = idx & 7;
            const float* src = xrow + (size_t)(lc * SCH + r) * XPAD + q * 4;
            uint32_t dst = sbase + (uint32_t)(((buf * SCH + r) * 8 + q) * 16);
            cp_async16(dst, src);
        }
        asm volatile("cp.async.commit_group;" ::: "memory");
    };

    load_chunk(0, 0);

    float u   = xc[base];
    float dtv = dt[base];
    float zv  = xz[zbase];

    for (int lc = 0; lc < LL / SCH; lc++) {
        const int buf = lc & 1;
        if (lc + 1 < LL / SCH) {
            load_chunk(lc + 1, 1 - buf);
            asm volatile("cp.async.wait_group 1;" ::: "memory");
        } else {
            asm volatile("cp.async.wait_group 0;" ::: "memory");
        }
        __syncthreads();

        #pragma unroll 4
        for (int ll = 0; ll < SCH; ll++) {
            const int l = lc * SCH + ll;
            float un = 0.f, dtn = 0.f, zn = 0.f;
            if (l + 1 < LL) {
                un  = xc[base + (size_t)(l+1)*DD];
                dtn = dt[base + (size_t)(l+1)*DD];
                zn  = xz[zbase + (size_t)(l+1)*(2*DD)];
            }
            float4 q0 = sBC[buf][ll][0], q1 = sBC[buf][ll][1];
            float4 q2 = sBC[buf][ll][2], q3 = sBC[buf][ll][3];
            float4 q4 = sBC[buf][ll][4], q5 = sBC[buf][ll][5];
            float4 q6 = sBC[buf][ll][6], q7 = sBC[buf][ll][7];
            float Bv[SSTATE] = {q0.x,q0.y,q0.z,q0.w, q1.x,q1.y,q1.z,q1.w,
                                q2.x,q2.y,q2.z,q2.w, q3.x,q3.y,q3.z,q3.w};
            float Cv[SSTATE] = {q4.x,q4.y,q4.z,q4.w, q5.x,q5.y,q5.z,q5.w,
                                q6.x,q6.y,q6.z,q6.w, q7.x,q7.y,q7.z,q7.w};

            float p1  = __expf(-dtv);
            float p2  = p1*p1;
            float p4  = p2*p2;
            float p8  = p4*p4;
            float p16 = p8*p8;
            float du  = dtv * u;

            float y0 = 0.f, y1 = 0.f, y2 = 0.f, y3 = 0.f;
            #pragma unroll
            for (int s = 0; s < SSTATE; s++) {
                const int e = s + 1;
                float pw = 1.0f;
                if (e & 1)  pw *= p1;
                if (e & 2)  pw *= p2;
                if (e & 4)  pw *= p4;
                if (e & 8)  pw *= p8;
                if (e & 16) pw *= p16;
                float dA = pw * fmaf(eps[s], dtv, 1.0f);
                h[s] = fmaf(dA, h[s], du * Bv[s]);
                float t2 = h[s] * Cv[s];
                if      ((s & 3) == 0) y0 += t2;
                else if ((s & 3) == 1) y1 += t2;
                else if ((s & 3) == 2) y2 += t2;
                else                   y3 += t2;
            }
            float ys = (y0 + y1) + (y2 + y3);
            float o  = fmaf(u, Dv, ys) * silu_f(zv);
            unsigned short oh, ol;
            split1(o, oh, ol);
            *(unsigned short*)(yh + base + (size_t)l*DD) = oh;
            *(unsigned short*)(yl + base + (size_t)l*DD) = ol;
            u = un; dtv = dtn; zv = zn;
        }
        __syncthreads();
    }
}

// ---------------- launch ---------------------------------------------------
extern "C" void kernel_launch(void* const* d_in, const int* in_sizes, int n_in,
                              void* d_out, int out_size)
{
    const float* x      = (const float*)d_in[0];
    const float* W_in   = (const float*)d_in[1];
    const float* conv_w = (const float*)d_in[2];
    const float* conv_b = (const float*)d_in[3];
    const float* W_x    = (const float*)d_in[4];
    const float* W_dt   = (const float*)d_in[5];
    const float* b_dt   = (const float*)d_in[6];
    const float* A_log  = (const float*)d_in[7];
    const float* D      = (const float*)d_in[8];
    const float* W_out  = (const float*)d_in[9];
    float* out = (float*)d_out;

    float *xz, *xc, *xdbl, *xpart, *dtb;
    __nv_bfloat16 *xh, *xl, *wih, *wil, *woh, *wol, *wdh, *wdl, *wxh, *wxl;
    __nv_bfloat16 *xch, *xcl, *dih, *dil, *yh, *yl;
    cudaGetSymbolAddress((void**)&xz,    g_xz);
    cudaGetSymbolAddress((void**)&xc,    g_xc);
    cudaGetSymbolAddress((void**)&xdbl,  g_xdbl);
    cudaGetSymbolAddress((void**)&xpart, g_xpart);
    cudaGetSymbolAddress((void**)&dtb,   g_dt);
    cudaGetSymbolAddress((void**)&xh,  g_xh);  cudaGetSymbolAddress((void**)&xl,  g_xl);
    cudaGetSymbolAddress((void**)&wih, g_wih); cudaGetSymbolAddress((void**)&wil, g_wil);
    cudaGetSymbolAddress((void**)&woh, g_woh); cudaGetSymbolAddress((void**)&wol, g_wol);
    cudaGetSymbolAddress((void**)&wdh, g_wdh); cudaGetSymbolAddress((void**)&wdl, g_wdl);
    cudaGetSymbolAddress((void**)&wxh, g_wxh); cudaGetSymbolAddress((void**)&wxl, g_wxl);
    cudaGetSymbolAddress((void**)&xch, g_xch); cudaGetSymbolAddress((void**)&xcl, g_xcl);
    cudaGetSymbolAddress((void**)&dih, g_dih); cudaGetSymbolAddress((void**)&dil, g_dil);
    cudaGetSymbolAddress((void**)&yh,  g_yh);  cudaGetSymbolAddress((void**)&yl,  g_yl);

    cudaFuncSetAttribute(mma_gemm256<0>, cudaFuncAttributeMaxDynamicSharedMemorySize, G_SMEM);
    cudaFuncSetAttribute(mma_gemm256<1>, cudaFuncAttributeMaxDynamicSharedMemorySize, G_SMEM);

    // idx0: split x
    split_kernel<<<(TT*HH/4 + 255)/256, 256>>>(x, xh, xl, TT*HH/4);
    // idx1: W_in^T split
    trsplit_kernel<<<dim3(2*DD/32, HH/32), dim3(32,8)>>>(W_in,  wih, wil, HH,  2*DD);
    // idx2: W_out^T split
    trsplit_kernel<<<dim3(HH/32,  DD/32),  dim3(32,8)>>>(W_out, woh, wol, DD,  HH);
    // idx3: GEMM1 (ncu capture slot): xz = x @ W_in  (2048 x 8192, K=2048)
    mma_gemm256<0><<<dim3(2*DD/128, TT/256), 256, G_SMEM>>>(
        xh, xl, wih, wil, xz, TT, 2*DD, HH, HH, nullptr);
    // idx4: W_dt^T split
    trsplit_kernel<<<dim3(DD/32,  RR/32),  dim3(32,8)>>>(W_dt,  wdh, wdl, RR,  DD);
    // idx5: W_x^T split (padded)
    trsplit_kernel<<<dim3(XDBL_N/32, DD/32), dim3(32,8)>>>(W_x, wxh, wxl, DD, XDBL_N);
    // idx6: conv + silu -> xc + bf16 split
    conv_silu_kernel<<<(TT*(DD/4) + 255)/256, 256>>>(xz, conv_w, conv_b, xc, xch, xcl);
    // idx7: x_dbl split-K
    mma_gemm256<0><<<dim3(XPAD/128, TT/256, NSPLITK), 256, G_SMEM>>>(
        xch, xcl, wxh, wxl, xpart, TT, XPAD, DD, DD/NSPLITK, nullptr);
    // idx8: reduce + dt_in split
    xdbl_reduce_kernel<<<(TT*(XPAD/4) + 255)/256, 256>>>(xpart, xdbl, dih, dil);
    // idx9: dt GEMM + softplus
    mma_gemm256<1><<<dim3(DD/128, TT/256), 256, G_SMEM>>>(
        dih, dil, wdh, wdl, dtb, TT, DD, RR, RR, b_dt);
    // idx10: scan + fused mix -> yh/yl
    scan_kernel<<<dim3(DD/128, BBATCH), 128>>>(xc, dtb, xdbl, A_log, xz, D, yh, yl);
    // idx11: out = y @ W_out  (2048 x 2048, K=4096)
    mma_gemm256<0><<<dim3(HH/128, TT/256), 256, G_SMEM>>>(
        yh, yl, woh, wol, out, TT, HH, DD, DD, nullptr);
}

// round 12
// speedup vs baseline: 1.3930x; 1.3930x over previous
#include <cuda_runtime.h>
#include <cuda_bf16.h>
#include <math.h>
#include <stdint.h>

// Problem dims (fixed)
#define BBATCH 2
#define LL   1024
#define HH   2048
#define DD   4096      // d = H*E
#define SSTATE 16
#define RR   128
#define TT   2048      // B*L tokens
#define XDBL_N 160     // R + 2S
#define XPAD 256       // padded x_dbl width
#define NSPLITK 8

// ---------------- scratch (static device globals; no allocation) ----------
__device__ float g_xz  [(size_t)TT * 2 * DD];
__device__ float g_xc  [(size_t)TT * DD];
__device__ float g_xdbl[(size_t)TT * XPAD];                 // padded
__device__ float g_xpart[(size_t)NSPLITK * TT * XPAD];      // split-K partials
__device__ float g_dt  [(size_t)TT * DD];

// bf16 split operands (hi/lo)
__device__ __nv_bfloat16 g_xh [(size_t)TT * HH];
__device__ __nv_bfloat16 g_xl [(size_t)TT * HH];
__device__ __nv_bfloat16 g_wih[(size_t)2 * DD * HH];   // W_in^T  [8192][2048]
__device__ __nv_bfloat16 g_wil[(size_t)2 * DD * HH];
__device__ __nv_bfloat16 g_woh[(size_t)HH * DD];       // W_out^T [2048][4096]
__device__ __nv_bfloat16 g_wol[(size_t)HH * DD];
__device__ __nv_bfloat16 g_wdh[(size_t)DD * RR];       // W_dt^T  [4096][128]
__device__ __nv_bfloat16 g_wdl[(size_t)DD * RR];
__device__ __nv_bfloat16 g_wxh[(size_t)XPAD * DD];     // W_x^T   [256(pad)][4096]
__device__ __nv_bfloat16 g_wxl[(size_t)XPAD * DD];
__device__ __nv_bfloat16 g_xch[(size_t)TT * DD];       // split of xc
__device__ __nv_bfloat16 g_xcl[(size_t)TT * DD];
__device__ __nv_bfloat16 g_dih[(size_t)TT * RR];       // dt_in   [2048][128]
__device__ __nv_bfloat16 g_dil[(size_t)TT * RR];
__device__ __nv_bfloat16 g_yh [(size_t)TT * DD];
__device__ __nv_bfloat16 g_yl [(size_t)TT * DD];

// ---------------- small helpers ------------------------------------------
__device__ __forceinline__ float silu_f(float x) { return x / (1.0f + __expf(-x)); }
__device__ __forceinline__ float softplus_f(float x) {
    return fmaxf(x, 0.0f) + log1pf(__expf(-fabsf(x)));
}
__device__ __forceinline__ uint32_t smem_u32(const void* p) {
    uint32_t a;
    asm("{ .reg .u64 t; cvta.to.shared.u64 t, %1; cvt.u32.u64 %0, t; }" : "=r"(a) : "l"(p));
    return a;
}
__device__ __forceinline__ unsigned short bf16_bits(__nv_bfloat16 h) {
    unsigned short u; *(__nv_bfloat16*)&u = h; return u;
}
__device__ __forceinline__ void split1(float v, unsigned short& h, unsigned short& l) {
    __nv_bfloat16 hb = __float2bfloat16(v);
    __nv_bfloat16 lb = __float2bfloat16(v - __bfloat162float(hb));
    h = bf16_bits(hb); l = bf16_bits(lb);
}
__device__ __forceinline__ void cp_async16(uint32_t dst, const void* src) {
    asm volatile("cp.async.cg.shared.global [%0], [%1], 16;" :: "r"(dst), "l"(src));
}
__device__ __forceinline__ void ldsm_x4(uint32_t addr, uint32_t& r0, uint32_t& r1,
                                        uint32_t& r2, uint32_t& r3) {
    asm volatile("ldmatrix.sync.aligned.m8n8.x4.shared.b16 {%0,%1,%2,%3}, [%4];"
                 : "=r"(r0), "=r"(r1), "=r"(r2), "=r"(r3) : "r"(addr));
}
__device__ __forceinline__ void mma_bf16(float* c, const uint32_t* a,
                                         uint32_t b0, uint32_t b1) {
    asm volatile(
        "mma.sync.aligned.m16n8k16.row.col.f32.bf16.bf16.f32 "
        "{%0,%1,%2,%3}, {%4,%5,%6,%7}, {%8,%9}, {%0,%1,%2,%3};"
        : "+f"(c[0]), "+f"(c[1]), "+f"(c[2]), "+f"(c[3])
        : "r"(a[0]), "r"(a[1]), "r"(a[2]), "r"(a[3]), "r"(b0), "r"(b1));
}

// ---------------- mma.sync split-bf16 GEMM, 256x128 tile ------------------
#define G_AT 32768                   // A tile bytes: 256 x 128B
#define G_BT 16384                   // B tile bytes: 128 x 128B
#define G_STAGE (2*G_AT + 2*G_BT)    // 96KB
#define G_SMEM (2*G_STAGE + 1024)

template<int EPI>
__global__ __launch_bounds__(256, 1)
void mma_gemm256(const __nv_bfloat16* __restrict__ Ah, const __nv_bfloat16* __restrict__ Al,
                 const __nv_bfloat16* __restrict__ Bh, const __nv_bfloat16* __restrict__ Bl,
                 float* __restrict__ C, int M, int N, int ldk,
                 int kLen, const float* __restrict__ bias)
{
    extern __shared__ char smem_raw[];
    const uint32_t sb = (smem_u32(smem_raw) + 1023u) & ~1023u;

    const int tid  = threadIdx.x;
    const int lane = tid & 31;
    const int wid  = tid >> 5;
    const int wm   = wid & 3;
    const int wn   = wid >> 2;
    const int bm = blockIdx.y * 256;
    const int bn = blockIdx.x * 128;
    const int kOff = blockIdx.z * kLen;
    C += (size_t)blockIdx.z * (size_t)M * (size_t)N;   // split-K partial plane

    uint32_t swA[8]; size_t gA[8];
    #pragma unroll
    for (int i = 0; i < 8; i++) {
        int c = i * 256 + tid;
        int row = c >> 3, kb = c & 7;
        uint32_t o = (uint32_t)(row * 128 + kb * 16);
        swA[i] = o ^ ((o >> 3) & 0x70);
        gA[i]  = (size_t)row * (size_t)ldk * 2 + (size_t)kb * 16;
    }
    uint32_t swB[4]; size_t gB[4];
    #pragma unroll
    for (int i = 0; i < 4; i++) {
        int c = i * 256 + tid;
        int row = c >> 3, kb = c & 7;
        uint32_t o = (uint32_t)(row * 128 + kb * 16);
        swB[i] = o ^ ((o >> 3) & 0x70);
        gB[i]  = (size_t)row * (size_t)ldk * 2 + (size_t)kb * 16;
    }
    const char* srcAh = (const char*)(Ah + (size_t)bm * ldk + kOff);
    const char* srcAl = (const char*)(Al + (size_t)bm * ldk + kOff);
    const char* srcBh = (const char*)(Bh + (size_t)bn * ldk + kOff);
    const char* srcBl = (const char*)(Bl + (size_t)bn * ldk + kOff);

    float acc[4][8][4];
    #pragma unroll
    for (int mi = 0; mi < 4; mi++)
        #pragma unroll
        for (int ni = 0; ni < 8; ni++)
            #pragma unroll
            for (int r = 0; r < 4; r++) acc[mi][ni][r] = 0.0f;

    const int NK = kLen >> 6;

    auto load_stage = [&](int kblk, int s) {
        uint32_t base = sb + (uint32_t)s * G_STAGE;
        size_t kadd = (size_t)kblk * 128;
        #pragma unroll
        for (int i = 0; i < 8; i++) cp_async16(base + swA[i],           srcAh + kadd + gA[i]);
        #pragma unroll
        for (int i = 0; i < 8; i++) cp_async16(base + G_AT + swA[i],    srcAl + kadd + gA[i]);
        #pragma unroll
        for (int i = 0; i < 4; i++) cp_async16(base + 2*G_AT + swB[i],  srcBh + kadd + gB[i]);
        #pragma unroll
        for (int i = 0; i < 4; i++) cp_async16(base + 2*G_AT + G_BT + swB[i], srcBl + kadd + gB[i]);
        asm volatile("cp.async.commit_group;" ::: "memory");
    };

    load_stage(0, 0);

    for (int kblk = 0; kblk < NK; kblk++) {
        int s = kblk & 1;
        if (kblk + 1 < NK) {
            load_stage(kblk + 1, 1 - s);
            asm volatile("cp.async.wait_group 1;" ::: "memory");
        } else {
            asm volatile("cp.async.wait_group 0;" ::: "memory");
        }
        __syncthreads();

        uint32_t base = sb + (uint32_t)s * G_STAGE;
        uint32_t tAh = base, tAl = base + G_AT;
        uint32_t tBh = base + 2*G_AT, tBl = base + 2*G_AT + G_BT;

        #pragma unroll
        for (int kk = 0; kk < 4; kk++) {
            const int kb = kk * 32;
            uint32_t aoff[4], boff[4];
            #pragma unroll
            for (int mi = 0; mi < 4; mi++) {
                int mrow = wm * 64 + mi * 16 + (lane & 15);
                int ko   = kb + ((lane >> 4) << 4);
                uint32_t o = (uint32_t)(mrow * 128 + ko);
                aoff[mi] = o ^ ((o >> 3) & 0x70);
            }
            #pragma unroll
            for (int nj = 0; nj < 4; nj++) {
                int nrow = wn * 64 + nj * 16 + (lane & 7) + ((lane >> 4) << 3);
                int ko   = kb + (((lane >> 3) & 1) << 4);
                uint32_t o = (uint32_t)(nrow * 128 + ko);
                boff[nj] = o ^ ((o >> 3) & 0x70);
            }

            uint32_t ah[16], bb[16], tt[16];
            #pragma unroll
            for (int mi = 0; mi < 4; mi++)
                ldsm_x4(tAh + aoff[mi], ah[mi*4+0], ah[mi*4+1], ah[mi*4+2], ah[mi*4+3]);
            #pragma unroll
            for (int nj = 0; nj < 4; nj++)
                ldsm_x4(tBh + boff[nj], bb[nj*4+0], bb[nj*4+1], bb[nj*4+2], bb[nj*4+3]);
            // pass 0: ah * bh
            #pragma unroll
            for (int mi = 0; mi < 4; mi++)
                #pragma unroll
                for (int ni = 0; ni < 8; ni++)
                    mma_bf16(acc[mi][ni], &ah[mi*4], bb[ni*2], bb[ni*2+1]);
            // pass 1: al * bh
            #pragma unroll
            for (int mi = 0; mi < 4; mi++)
                ldsm_x4(tAl + aoff[mi], tt[mi*4+0], tt[mi*4+1], tt[mi*4+2], tt[mi*4+3]);
            #pragma unroll
            for (int mi = 0; mi < 4; mi++)
                #pragma unroll
                for (int ni = 0; ni < 8; ni++)
                    mma_bf16(acc[mi][ni], &tt[mi*4], bb[ni*2], bb[ni*2+1]);
            // pass 2: ah * bl
            #pragma unroll
            for (int nj = 0; nj < 4; nj++)
                ldsm_x4(tBl + boff[nj], tt[nj*4+0], tt[nj*4+1], tt[nj*4+2], tt[nj*4+3]);
            #pragma unroll
            for (int mi = 0; mi < 4; mi++)
                #pragma unroll
                for (int ni = 0; ni < 8; ni++)
                    mma_bf16(acc[mi][ni], &ah[mi*4], tt[ni*2], tt[ni*2+1]);
        }
        __syncthreads();
    }

    #pragma unroll
    for (int mi = 0; mi < 4; mi++) {
        #pragma unroll
        for (int ni = 0; ni < 8; ni++) {
            int row = bm + wm * 64 + mi * 16 + (lane >> 2);
            int col = bn + wn * 64 + ni * 8 + (lane & 3) * 2;
            float2 v0 = make_float2(acc[mi][ni][0], acc[mi][ni][1]);
            float2 v1 = make_float2(acc[mi][ni][2], acc[mi][ni][3]);
            if (EPI == 1) {
                float b0 = __ldg(bias + col), b1 = __ldg(bias + col + 1);
                v0.x = softplus_f(v0.x + b0); v0.y = softplus_f(v0.y + b1);
                v1.x = softplus_f(v1.x + b0); v1.y = softplus_f(v1.y + b1);
            }
            *(float2*)(C + (size_t)row * N + col)       = v0;
            *(float2*)(C + (size_t)(row + 8) * N + col) = v1;
        }
    }
}

// ---------------- prep kernels --------------------------------------------
__global__ __launch_bounds__(256)
void split_kernel(const float* __restrict__ in, __nv_bfloat16* __restrict__ hi,
                  __nv_bfloat16* __restrict__ lo, int n4)
{
    int i = blockIdx.x * 256 + threadIdx.x;
    if (i >= n4) return;
    float4 v = ((const float4*)in)[i];
    ushort4 h, l;
    split1(v.x, h.x, l.x); split1(v.y, h.y, l.y);
    split1(v.z, h.z, l.z); split1(v.w, h.w, l.w);
    ((ushort4*)hi)[i] = h;
    ((ushort4*)lo)[i] = l;
}

// in: [R][C] fp32 -> outH/L: [C][R] bf16  (R, C multiples of 32)
__global__ __launch_bounds__(256)
void trsplit_kernel(const float* __restrict__ in, __nv_bfloat16* __restrict__ oh,
                    __nv_bfloat16* __restrict__ ol, int R, int C)
{
    __shared__ float t[32][33];
    int c0 = blockIdx.x * 32, r0 = blockIdx.y * 32;
    int tx = threadIdx.x, ty = threadIdx.y;
    #pragma unroll
    for (int j = 0; j < 4; j++)
        t[ty + 8 * j][tx] = in[(size_t)(r0 + ty + 8 * j) * C + c0 + tx];
    __syncthreads();
    #pragma unroll
    for (int j = 0; j < 4; j++) {
        float v = t[tx][ty + 8 * j];
        unsigned short h, l; split1(v, h, l);
        size_t o = (size_t)(c0 + ty + 8 * j) * R + r0 + tx;
        *(unsigned short*)(oh + o) = h;
        *(unsigned short*)(ol + o) = l;
    }
}

// reduce split-K partials -> xdbl (padded) + fused dt_in bf16 split
__global__ __launch_bounds__(256)
void xdbl_reduce_kernel(const float* __restrict__ part, float* __restrict__ xdbl,
                        __nv_bfloat16* __restrict__ dih, __nv_bfloat16* __restrict__ dil)
{
    int i = blockIdx.x * 256 + threadIdx.x;
    if (i >= TT * (XPAD / 4)) return;
    float4 s = make_float4(0.f, 0.f, 0.f, 0.f);
    #pragma unroll
    for (int z = 0; z < NSPLITK; z++) {
        float4 v = ((const float4*)(part + (size_t)z * TT * XPAD))[i];
        s.x += v.x; s.y += v.y; s.z += v.z; s.w += v.w;
    }
    ((float4*)xdbl)[i] = s;
    int col = (i & (XPAD/4 - 1)) * 4;
    if (col < RR) {
        int row = i / (XPAD/4);
        ushort4 h, l;
        split1(s.x, h.x, l.x); split1(s.y, h.y, l.y);
        split1(s.z, h.z, l.z); split1(s.w, h.w, l.w);
        size_t o = ((size_t)row * RR + col) >> 2;
        ((ushort4*)dih)[o] = h;
        ((ushort4*)dil)[o] = l;
    }
}

// ---------------- depthwise conv3 + bias + SiLU (+ bf16 split out) --------
__global__ __launch_bounds__(256)
void conv_silu_kernel(const float* __restrict__ xz, const float* __restrict__ w,
                      const float* __restrict__ bias, float* __restrict__ xc,
                      __nv_bfloat16* __restrict__ xch, __nv_bfloat16* __restrict__ xcl)
{
    int i = blockIdx.x * blockDim.x + threadIdx.x;
    const int NW = TT * (DD/4);
    if (i >= NW) return;
    int c4 = i % (DD/4);
    int t  = i / (DD/4);
    int l  = t & (LL - 1);
    int c  = c4 * 4;

    const float* p = xz + (size_t)t * (2*DD) + c;
    float4 x0 = *(const float4*)p;
    float4 xm = (l > 0)      ? *(const float4*)(p - 2*DD) : make_float4(0,0,0,0);
    float4 xp = (l < LL - 1) ? *(const float4*)(p + 2*DD) : make_float4(0,0,0,0);

    float xmv[4] = {xm.x, xm.y, xm.z, xm.w};
    float x0v[4] = {x0.x, x0.y, x0.z, x0.w};
    float xpv[4] = {xp.x, xp.y, xp.z, xp.w};
    float out[4];
    #pragma unroll
    for (int j = 0; j < 4; j++) {
        int cc = c + j;
        float v = xmv[j]*w[cc*3+0] + x0v[j]*w[cc*3+1] + xpv[j]*w[cc*3+2] + bias[cc];
        out[j] = silu_f(v);
    }
    *(float4*)(xc + (size_t)t*DD + c) = make_float4(out[0], out[1], out[2], out[3]);
    ushort4 h, l4;
    split1(out[0], h.x, l4.x); split1(out[1], h.y, l4.y);
    split1(out[2], h.z, l4.z); split1(out[3], h.w, l4.w);
    size_t o = ((size_t)t*DD + c) >> 2;
    ((ushort4*)xch)[o] = h;
    ((ushort4*)xcl)[o] = l4;
}

// ---------------- selective scan + fused gated mix ------------------------
// ALL streams (u, dt, z, B/C) staged through dynamic smem in 32-step chunks,
// cp.async double-buffered. Prefetch distance = 32 steps (~4000 cyc) >> DRAM
// latency; inner loop is pure LDS + FMA.
#define SCH 32
#define SNC (LL / SCH)
// dynamic smem layout (floats):
//  sU  [2][SCH][128] @ 0       (8192)
//  sDT [2][SCH][128] @ 8192
//  sZ  [2][SCH][128] @ 16384
//  sBC [2][SCH][32]  @ 24576   (2048)
#define SCAN_SMEM ((24576 + 2048) * 4)

__global__ __launch_bounds__(128)
void scan_kernel(const float* __restrict__ xc, const float* __restrict__ dt,
                 const float* __restrict__ xdbl, const float* __restrict__ A_log,
                 const float* __restrict__ xz, const float* __restrict__ Dp,
                 __nv_bfloat16* __restrict__ yh, __nv_bfloat16* __restrict__ yl)
{
    extern __shared__ float sm[];
    float* sU  = sm;
    float* sDT = sm + 8192;
    float* sZ  = sm + 16384;
    float* sBC = sm + 24576;

    const int tid = threadIdx.x;
    const int c0  = blockIdx.x * 128;
    const int c   = c0 + tid;
    const int b   = blockIdx.y;

    float eps[SSTATE];
    #pragma unroll
    for (int s = 0; s < SSTATE; s++)
        eps[s] = (float)(s + 1) - expf(A_log[(size_t)c*SSTATE + s]);
    const float Dv = Dp[c];

    float h[SSTATE];
    #pragma unroll
    for (int s = 0; s < SSTATE; s++) h[s] = 0.0f;

    const float* xcrow = xc   + (size_t)b * LL * DD + c0;          // + l*DD
    const float* dtrow = dt   + (size_t)b * LL * DD + c0;          // + l*DD
    const float* zrow  = xz   + (size_t)b * LL * (2*DD) + DD + c0; // + l*2*DD
    const float* bcrow = xdbl + (size_t)b * LL * XPAD + RR;        // + l*XPAD

    const uint32_t sb = smem_u32(sm);
    auto load_chunk = [&](int lc, int buf) {
        const int l0 = lc * SCH;
        // U/DT/Z: 32 rows x 512B = 1024 16B-chunks each; 8 per thread
        #pragma unroll
        for (int k = 0; k < 8; k++) {
            int idx = k * 128 + tid;
            int r = idx >> 5, q = idx & 31;             // row, 16B chunk
            uint32_t so = (uint32_t)(((buf * SCH + r) * 128 + q * 4) * 4);
            cp_async16(sb + so,           xcrow + (size_t)(l0 + r) * DD     + q * 4);
            cp_async16(sb + 32768 + so,   dtrow + (size_t)(l0 + r) * DD     + q * 4);
            cp_async16(sb + 65536 + so,   zrow  + (size_t)(l0 + r) * (2*DD) + q * 4);
        }
        // BC: 32 rows x 128B = 256 chunks; 2 per thread
        #pragma unroll
        for (int k = 0; k < 2; k++) {
            int idx = k * 128 + tid;
            int r = idx >> 3, q = idx & 7;
            uint32_t so = (uint32_t)(98304 + ((buf * SCH + r) * 32 + q * 4) * 4);
            cp_async16(sb + so, bcrow + (size_t)(l0 + r) * XPAD + q * 4);
        }
        asm volatile("cp.async.commit_group;" ::: "memory");
    };

    load_chunk(0, 0);

    for (int lc = 0; lc < SNC; lc++) {
        const int buf = lc & 1;
        if (lc + 1 < SNC) {
            load_chunk(lc + 1, 1 - buf);
            asm volatile("cp.async.wait_group 1;" ::: "memory");
        } else {
            asm volatile("cp.async.wait_group 0;" ::: "memory");
        }
        __syncthreads();

        #pragma unroll 4
        for (int ll = 0; ll < SCH; ll++) {
            const int l = lc * SCH + ll;
            const int ro = (buf * SCH + ll);
            float u   = sU [ro * 128 + tid];
            float dtv = sDT[ro * 128 + tid];
            float zv  = sZ [ro * 128 + tid];
            const float4* bc = (const float4*)&sBC[ro * 32];
            float4 q0 = bc[0], q1 = bc[1], q2 = bc[2], q3 = bc[3];
            float4 q4 = bc[4], q5 = bc[5], q6 = bc[6], q7 = bc[7];
            float Bv[SSTATE] = {q0.x,q0.y,q0.z,q0.w, q1.x,q1.y,q1.z,q1.w,
                                q2.x,q2.y,q2.z,q2.w, q3.x,q3.y,q3.z,q3.w};
            float Cv[SSTATE] = {q4.x,q4.y,q4.z,q4.w, q5.x,q5.y,q5.z,q5.w,
                                q6.x,q6.y,q6.z,q6.w, q7.x,q7.y,q7.z,q7.w};

            float p1  = __expf(-dtv);
            float p2  = p1*p1;
            float p4  = p2*p2;
            float p8  = p4*p4;
            float p16 = p8*p8;
            float du  = dtv * u;

            float y0 = 0.f, y1 = 0.f, y2 = 0.f, y3 = 0.f;
            #pragma unroll
            for (int s = 0; s < SSTATE; s++) {
                const int e = s + 1;
                float pw = 1.0f;
                if (e & 1)  pw *= p1;
                if (e & 2)  pw *= p2;
                if (e & 4)  pw *= p4;
                if (e & 8)  pw *= p8;
                if (e & 16) pw *= p16;
                float dA = pw * fmaf(eps[s], dtv, 1.0f);
                h[s] = fmaf(dA, h[s], du * Bv[s]);
                float t2 = h[s] * Cv[s];
                if      ((s & 3) == 0) y0 += t2;
                else if ((s & 3) == 1) y1 += t2;
                else if ((s & 3) == 2) y2 += t2;
                else                   y3 += t2;
            }
            float ys = (y0 + y1) + (y2 + y3);
            float o  = fmaf(u, Dv, ys) * silu_f(zv);
            unsigned short oh, ol;
            split1(o, oh, ol);
            size_t oidx = (size_t)b * LL * DD + (size_t)l * DD + c;
            *(unsigned short*)(yh + oidx) = oh;
            *(unsigned short*)(yl + oidx) = ol;
        }
        __syncthreads();
    }
}

// ---------------- launch ---------------------------------------------------
extern "C" void kernel_launch(void* const* d_in, const int* in_sizes, int n_in,
                              void* d_out, int out_size)
{
    const float* x      = (const float*)d_in[0];
    const float* W_in   = (const float*)d_in[1];
    const float* conv_w = (const float*)d_in[2];
    const float* conv_b = (const float*)d_in[3];
    const float* W_x    = (const float*)d_in[4];
    const float* W_dt   = (const float*)d_in[5];
    const float* b_dt   = (const float*)d_in[6];
    const float* A_log  = (const float*)d_in[7];
    const float* D      = (const float*)d_in[8];
    const float* W_out  = (const float*)d_in[9];
    float* out = (float*)d_out;

    float *xz, *xc, *xdbl, *xpart, *dtb;
    __nv_bfloat16 *xh, *xl, *wih, *wil, *woh, *wol, *wdh, *wdl, *wxh, *wxl;
    __nv_bfloat16 *xch, *xcl, *dih, *dil, *yh, *yl;
    cudaGetSymbolAddress((void**)&xz,    g_xz);
    cudaGetSymbolAddress((void**)&xc,    g_xc);
    cudaGetSymbolAddress((void**)&xdbl,  g_xdbl);
    cudaGetSymbolAddress((void**)&xpart, g_xpart);
    cudaGetSymbolAddress((void**)&dtb,   g_dt);
    cudaGetSymbolAddress((void**)&xh,  g_xh);  cudaGetSymbolAddress((void**)&xl,  g_xl);
    cudaGetSymbolAddress((void**)&wih, g_wih); cudaGetSymbolAddress((void**)&wil, g_wil);
    cudaGetSymbolAddress((void**)&woh, g_woh); cudaGetSymbolAddress((void**)&wol, g_wol);
    cudaGetSymbolAddress((void**)&wdh, g_wdh); cudaGetSymbolAddress((void**)&wdl, g_wdl);
    cudaGetSymbolAddress((void**)&wxh, g_wxh); cudaGetSymbolAddress((void**)&wxl, g_wxl);
    cudaGetSymbolAddress((void**)&xch, g_xch); cudaGetSymbolAddress((void**)&xcl, g_xcl);
    cudaGetSymbolAddress((void**)&dih, g_dih); cudaGetSymbolAddress((void**)&dil, g_dil);
    cudaGetSymbolAddress((void**)&yh,  g_yh);  cudaGetSymbolAddress((void**)&yl,  g_yl);

    cudaFuncSetAttribute(mma_gemm256<0>, cudaFuncAttributeMaxDynamicSharedMemorySize, G_SMEM);
    cudaFuncSetAttribute(mma_gemm256<1>, cudaFuncAttributeMaxDynamicSharedMemorySize, G_SMEM);
    cudaFuncSetAttribute(scan_kernel,    cudaFuncAttributeMaxDynamicSharedMemorySize, SCAN_SMEM);

    // idx0: split x
    split_kernel<<<(TT*HH/4 + 255)/256, 256>>>(x, xh, xl, TT*HH/4);
    // idx1: W_in^T split
    trsplit_kernel<<<dim3(2*DD/32, HH/32), dim3(32,8)>>>(W_in,  wih, wil, HH,  2*DD);
    // idx2: W_out^T split
    trsplit_kernel<<<dim3(HH/32,  DD/32),  dim3(32,8)>>>(W_out, woh, wol, DD,  HH);
    // idx3: GEMM1 (ncu capture slot): xz = x @ W_in  (2048 x 8192, K=2048)
    mma_gemm256<0><<<dim3(2*DD/128, TT/256), 256, G_SMEM>>>(
        xh, xl, wih, wil, xz, TT, 2*DD, HH, HH, nullptr);
    // idx4: W_dt^T split
    trsplit_kernel<<<dim3(DD/32,  RR/32),  dim3(32,8)>>>(W_dt,  wdh, wdl, RR,  DD);
    // idx5: W_x^T split (padded)
    trsplit_kernel<<<dim3(XDBL_N/32, DD/32), dim3(32,8)>>>(W_x, wxh, wxl, DD, XDBL_N);
    // idx6: conv + silu -> xc + bf16 split
    conv_silu_kernel<<<(TT*(DD/4) + 255)/256, 256>>>(xz, conv_w, conv_b, xc, xch, xcl);
    // idx7: x_dbl split-K
    mma_gemm256<0><<<dim3(XPAD/128, TT/256, NSPLITK), 256, G_SMEM>>>(
        xch, xcl, wxh, wxl, xpart, TT, XPAD, DD, DD/NSPLITK, nullptr);
    // idx8: reduce + dt_in split
    xdbl_reduce_kernel<<<(TT*(XPAD/4) + 255)/256, 256>>>(xpart, xdbl, dih, dil);
    // idx9: dt GEMM + softplus
    mma_gemm256<1><<<dim3(DD/128, TT/256), 256, G_SMEM>>>(
        dih, dil, wdh, wdl, dtb, TT, DD, RR, RR, b_dt);
    // idx10: scan + fused mix -> yh/yl
    scan_kernel<<<dim3(DD/128, BBATCH), 128, SCAN_SMEM>>>(
        xc, dtb, xdbl, A_log, xz, D, yh, yl);
    // idx11: out = y @ W_out  (2048 x 2048, K=4096)
    mma_gemm256<0><<<dim3(HH/128, TT/256), 256, G_SMEM>>>(
        yh, yl, woh, wol, out, TT, HH, DD, DD, nullptr);
}

// round 13
// speedup vs baseline: 1.8450x; 1.3244x over previous
#include <cuda_runtime.h>
#include <cuda_bf16.h>
#include <cuda_fp16.h>
#include <math.h>
#include <stdint.h>

// Problem dims (fixed)
#define BBATCH 2
#define LL   1024
#define HH   2048
#define DD   4096      // d = H*E
#define SSTATE 16
#define RR   128
#define TT   2048      // B*L tokens
#define XDBL_N 160     // R + 2S
#define XPAD 256       // padded x_dbl width
#define NSPLITK 8

// ---------------- scratch (static device globals; no allocation) ----------
__device__ float g_xz  [(size_t)TT * 2 * DD];
__device__ float g_xc  [(size_t)TT * DD];
__device__ float g_xdbl[(size_t)TT * XPAD];                 // padded
__device__ float g_xpart[(size_t)NSPLITK * TT * XPAD];      // split-K partials
__device__ float g_dt  [(size_t)TT * DD];

// fp16 split operands (GEMM1 / out-GEMM, 2-pass)
__device__ __half g_xh [(size_t)TT * HH];
__device__ __half g_xl [(size_t)TT * HH];
__device__ __half g_wih[(size_t)2 * DD * HH];   // W_in^T  [8192][2048] (hi only used)
__device__ __half g_woh[(size_t)HH * DD];       // W_out^T [2048][4096] (hi only used)
__device__ __half g_yh [(size_t)TT * DD];
__device__ __half g_yl [(size_t)TT * DD];

// bf16 split operands (dt path, 3-pass — proven accuracy)
__device__ __nv_bfloat16 g_wdh[(size_t)DD * RR];       // W_dt^T  [4096][128]
__device__ __nv_bfloat16 g_wdl[(size_t)DD * RR];
__device__ __nv_bfloat16 g_wxh[(size_t)XPAD * DD];     // W_x^T   [256(pad)][4096]
__device__ __nv_bfloat16 g_wxl[(size_t)XPAD * DD];
__device__ __nv_bfloat16 g_xch[(size_t)TT * DD];       // split of xc
__device__ __nv_bfloat16 g_xcl[(size_t)TT * DD];
__device__ __nv_bfloat16 g_dih[(size_t)TT * RR];       // dt_in   [2048][128]
__device__ __nv_bfloat16 g_dil[(size_t)TT * RR];

// ---------------- small helpers ------------------------------------------
__device__ __forceinline__ float silu_f(float x) { return x / (1.0f + __expf(-x)); }
__device__ __forceinline__ float softplus_f(float x) {
    return fmaxf(x, 0.0f) + log1pf(__expf(-fabsf(x)));
}
__device__ __forceinline__ uint32_t smem_u32(const void* p) {
    uint32_t a;
    asm("{ .reg .u64 t; cvta.to.shared.u64 t, %1; cvt.u32.u64 %0, t; }" : "=r"(a) : "l"(p));
    return a;
}
__device__ __forceinline__ unsigned short bf16_bits(__nv_bfloat16 h) {
    unsigned short u; *(__nv_bfloat16*)&u = h; return u;
}
__device__ __forceinline__ void split1(float v, unsigned short& h, unsigned short& l) {
    __nv_bfloat16 hb = __float2bfloat16(v);
    __nv_bfloat16 lb = __float2bfloat16(v - __bfloat162float(hb));
    h = bf16_bits(hb); l = bf16_bits(lb);
}
__device__ __forceinline__ unsigned short h_bits(__half h) {
    unsigned short u; *(__half*)&u = h; return u;
}
__device__ __forceinline__ void split1h(float v, unsigned short& h, unsigned short& l) {
    __half hb = __float2half(v);
    __half lb = __float2half(v - __half2float(hb));
    h = h_bits(hb); l = h_bits(lb);
}
__device__ __forceinline__ void cp_async16(uint32_t dst, const void* src) {
    asm volatile("cp.async.cg.shared.global [%0], [%1], 16;" :: "r"(dst), "l"(src));
}
__device__ __forceinline__ void ldsm_x4(uint32_t addr, uint32_t& r0, uint32_t& r1,
                                        uint32_t& r2, uint32_t& r3) {
    asm volatile("ldmatrix.sync.aligned.m8n8.x4.shared.b16 {%0,%1,%2,%3}, [%4];"
                 : "=r"(r0), "=r"(r1), "=r"(r2), "=r"(r3) : "r"(addr));
}
__device__ __forceinline__ void mma_bf16(float* c, const uint32_t* a,
                                         uint32_t b0, uint32_t b1) {
    asm volatile(
        "mma.sync.aligned.m16n8k16.row.col.f32.bf16.bf16.f32 "
        "{%0,%1,%2,%3}, {%4,%5,%6,%7}, {%8,%9}, {%0,%1,%2,%3};"
        : "+f"(c[0]), "+f"(c[1]), "+f"(c[2]), "+f"(c[3])
        : "r"(a[0]), "r"(a[1]), "r"(a[2]), "r"(a[3]), "r"(b0), "r"(b1));
}
__device__ __forceinline__ void mma_f16(float* c, const uint32_t* a,
                                        uint32_t b0, uint32_t b1) {
    asm volatile(
        "mma.sync.aligned.m16n8k16.row.col.f32.f16.f16.f32 "
        "{%0,%1,%2,%3}, {%4,%5,%6,%7}, {%8,%9}, {%0,%1,%2,%3};"
        : "+f"(c[0]), "+f"(c[1]), "+f"(c[2]), "+f"(c[3])
        : "r"(a[0]), "r"(a[1]), "r"(a[2]), "r"(a[3]), "r"(b0), "r"(b1));
}

// ======== fp16 2-pass GEMM: 128x128 tile, 2 CTAs/SM ========================
// C[M,N] = (Ah+Al) @ Bh^T.  BK=64, 2-stage cp.async, 256 threads,
// warp tile 32x64.  Stage = Ah,Al,Bh tiles (48KB) -> 96KB smem -> 2 CTA/SM.
#define H_AT 16384
#define H_STAGE (3*H_AT)
#define H_SMEM (2*H_STAGE + 1024)

__global__ __launch_bounds__(256, 2)
void mma_gemm128h(const __half* __restrict__ Ah, const __half* __restrict__ Al,
                  const __half* __restrict__ Bh,
                  float* __restrict__ C, int M, int N, int ldk, int kLen)
{
    extern __shared__ char smem_raw[];
    const uint32_t sb = (smem_u32(smem_raw) + 1023u) & ~1023u;

    const int tid  = threadIdx.x;
    const int lane = tid & 31;
    const int wid  = tid >> 5;
    const int wm   = wid & 3;        // 4 m-slabs of 32
    const int wn   = wid >> 2;       // 2 n-slabs of 64
    const int bm = blockIdx.y * 128;
    const int bn = blockIdx.x * 128;

    uint32_t sw[4]; uint32_t gofs[4];
    #pragma unroll
    for (int i = 0; i < 4; i++) {
        int c = i * 256 + tid;
        int row = c >> 3, kb = c & 7;
        uint32_t o = (uint32_t)(row * 128 + kb * 16);
        sw[i]   = o ^ ((o >> 3) & 0x70);
        gofs[i] = (uint32_t)(row * ldk * 2 + kb * 16);
    }
    const char* srcAh = (const char*)(Ah + (size_t)bm * ldk);
    const char* srcAl = (const char*)(Al + (size_t)bm * ldk);
    const char* srcBh = (const char*)(Bh + (size_t)bn * ldk);

    float acc[2][8][4];
    #pragma unroll
    for (int mi = 0; mi < 2; mi++)
        #pragma unroll
        for (int ni = 0; ni < 8; ni++)
            #pragma unroll
            for (int r = 0; r < 4; r++) acc[mi][ni][r] = 0.0f;

    const int NK = kLen >> 6;

    auto load_stage = [&](int kblk, int s) {
        uint32_t base = sb + (uint32_t)s * H_STAGE;
        uint32_t kadd = (uint32_t)kblk * 128;
        #pragma unroll
        for (int i = 0; i < 4; i++) cp_async16(base + sw[i],            srcAh + kadd + gofs[i]);
        #pragma unroll
        for (int i = 0; i < 4; i++) cp_async16(base + H_AT + sw[i],     srcAl + kadd + gofs[i]);
        #pragma unroll
        for (int i = 0; i < 4; i++) cp_async16(base + 2*H_AT + sw[i],   srcBh + kadd + gofs[i]);
        asm volatile("cp.async.commit_group;" ::: "memory");
    };

    load_stage(0, 0);

    for (int kblk = 0; kblk < NK; kblk++) {
        int s = kblk & 1;
        if (kblk + 1 < NK) {
            load_stage(kblk + 1, 1 - s);
            asm volatile("cp.async.wait_group 1;" ::: "memory");
        } else {
            asm volatile("cp.async.wait_group 0;" ::: "memory");
        }
        __syncthreads();

        uint32_t base = sb + (uint32_t)s * H_STAGE;
        uint32_t tAh = base, tAl = base + H_AT, tBh = base + 2*H_AT;

        #pragma unroll
        for (int kk = 0; kk < 4; kk++) {
            const int kb = kk * 32;
            uint32_t aoff[2], boff[4];
            #pragma unroll
            for (int mi = 0; mi < 2; mi++) {
                int mrow = wm * 32 + mi * 16 + (lane & 15);
                int ko   = kb + ((lane >> 4) << 4);
                uint32_t o = (uint32_t)(mrow * 128 + ko);
                aoff[mi] = o ^ ((o >> 3) & 0x70);
            }
            #pragma unroll
            for (int nj = 0; nj < 4; nj++) {
                int nrow = wn * 64 + nj * 16 + (lane & 7) + ((lane >> 4) << 3);
                int ko   = kb + (((lane >> 3) & 1) << 4);
                uint32_t o = (uint32_t)(nrow * 128 + ko);
                boff[nj] = o ^ ((o >> 3) & 0x70);
            }

            uint32_t ah[8], bb[16], tt[8];
            #pragma unroll
            for (int mi = 0; mi < 2; mi++)
                ldsm_x4(tAh + aoff[mi], ah[mi*4+0], ah[mi*4+1], ah[mi*4+2], ah[mi*4+3]);
            #pragma unroll
            for (int nj = 0; nj < 4; nj++)
                ldsm_x4(tBh + boff[nj], bb[nj*4+0], bb[nj*4+1], bb[nj*4+2], bb[nj*4+3]);
            // pass 0: ah * bh
            #pragma unroll
            for (int mi = 0; mi < 2; mi++)
                #pragma unroll
                for (int ni = 0; ni < 8; ni++)
                    mma_f16(acc[mi][ni], &ah[mi*4], bb[ni*2], bb[ni*2+1]);
            // pass 1: al * bh
            #pragma unroll
            for (int mi = 0; mi < 2; mi++)
                ldsm_x4(tAl + aoff[mi], tt[mi*4+0], tt[mi*4+1], tt[mi*4+2], tt[mi*4+3]);
            #pragma unroll
            for (int mi = 0; mi < 2; mi++)
                #pragma unroll
                for (int ni = 0; ni < 8; ni++)
                    mma_f16(acc[mi][ni], &tt[mi*4], bb[ni*2], bb[ni*2+1]);
        }
        __syncthreads();
    }

    #pragma unroll
    for (int mi = 0; mi < 2; mi++) {
        #pragma unroll
        for (int ni = 0; ni < 8; ni++) {
            int row = bm + wm * 32 + mi * 16 + (lane >> 2);
            int col = bn + wn * 64 + ni * 8 + (lane & 3) * 2;
            *(float2*)(C + (size_t)row * N + col)       = make_float2(acc[mi][ni][0], acc[mi][ni][1]);
            *(float2*)(C + (size_t)(row + 8) * N + col) = make_float2(acc[mi][ni][2], acc[mi][ni][3]);
        }
    }
}

// ======== bf16 3-pass GEMM: 256x128 tile (dt path, proven) =================
#define G_AT 32768
#define G_BT 16384
#define G_STAGE (2*G_AT + 2*G_BT)    // 96KB
#define G_SMEM (2*G_STAGE + 1024)

template<int EPI>
__global__ __launch_bounds__(256, 1)
void mma_gemm256(const __nv_bfloat16* __restrict__ Ah, const __nv_bfloat16* __restrict__ Al,
                 const __nv_bfloat16* __restrict__ Bh, const __nv_bfloat16* __restrict__ Bl,
                 float* __restrict__ C, int M, int N, int ldk,
                 int kLen, const float* __restrict__ bias)
{
    extern __shared__ char smem_raw[];
    const uint32_t sb = (smem_u32(smem_raw) + 1023u) & ~1023u;

    const int tid  = threadIdx.x;
    const int lane = tid & 31;
    const int wid  = tid >> 5;
    const int wm   = wid & 3;
    const int wn   = wid >> 2;
    const int bm = blockIdx.y * 256;
    const int bn = blockIdx.x * 128;
    const int kOff = blockIdx.z * kLen;
    C += (size_t)blockIdx.z * (size_t)M * (size_t)N;

    uint32_t swA[8]; size_t gA[8];
    #pragma unroll
    for (int i = 0; i < 8; i++) {
        int c = i * 256 + tid;
        int row = c >> 3, kb = c & 7;
        uint32_t o = (uint32_t)(row * 128 + kb * 16);
        swA[i] = o ^ ((o >> 3) & 0x70);
        gA[i]  = (size_t)row * (size_t)ldk * 2 + (size_t)kb * 16;
    }
    uint32_t swB[4]; size_t gB[4];
    #pragma unroll
    for (int i = 0; i < 4; i++) {
        int c = i * 256 + tid;
        int row = c >> 3, kb = c & 7;
        uint32_t o = (uint32_t)(row * 128 + kb * 16);
        swB[i] = o ^ ((o >> 3) & 0x70);
        gB[i]  = (size_t)row * (size_t)ldk * 2 + (size_t)kb * 16;
    }
    const char* srcAh = (const char*)(Ah + (size_t)bm * ldk + kOff);
    const char* srcAl = (const char*)(Al + (size_t)bm * ldk + kOff);
    const char* srcBh = (const char*)(Bh + (size_t)bn * ldk + kOff);
    const char* srcBl = (const char*)(Bl + (size_t)bn * ldk + kOff);

    float acc[4][8][4];
    #pragma unroll
    for (int mi = 0; mi < 4; mi++)
        #pragma unroll
        for (int ni = 0; ni < 8; ni++)
            #pragma unroll
            for (int r = 0; r < 4; r++) acc[mi][ni][r] = 0.0f;

    const int NK = kLen >> 6;

    auto load_stage = [&](int kblk, int s) {
        uint32_t base = sb + (uint32_t)s * G_STAGE;
        size_t kadd = (size_t)kblk * 128;
        #pragma unroll
        for (int i = 0; i < 8; i++) cp_async16(base + swA[i],           srcAh + kadd + gA[i]);
        #pragma unroll
        for (int i = 0; i < 8; i++) cp_async16(base + G_AT + swA[i],    srcAl + kadd + gA[i]);
        #pragma unroll
        for (int i = 0; i < 4; i++) cp_async16(base + 2*G_AT + swB[i],  srcBh + kadd + gB[i]);
        #pragma unroll
        for (int i = 0; i < 4; i++) cp_async16(base + 2*G_AT + G_BT + swB[i], srcBl + kadd + gB[i]);
        asm volatile("cp.async.commit_group;" ::: "memory");
    };

    load_stage(0, 0);

    for (int kblk = 0; kblk < NK; kblk++) {
        int s = kblk & 1;
        if (kblk + 1 < NK) {
            load_stage(kblk + 1, 1 - s);
            asm volatile("cp.async.wait_group 1;" ::: "memory");
        } else {
            asm volatile("cp.async.wait_group 0;" ::: "memory");
        }
        __syncthreads();

        uint32_t base = sb + (uint32_t)s * G_STAGE;
        uint32_t tAh = base, tAl = base + G_AT;
        uint32_t tBh = base + 2*G_AT, tBl = base + 2*G_AT + G_BT;

        #pragma unroll
        for (int kk = 0; kk < 4; kk++) {
            const int kb = kk * 32;
            uint32_t aoff[4], boff[4];
            #pragma unroll
            for (int mi = 0; mi < 4; mi++) {
                int mrow = wm * 64 + mi * 16 + (lane & 15);
                int ko   = kb + ((lane >> 4) << 4);
                uint32_t o = (uint32_t)(mrow * 128 + ko);
                aoff[mi] = o ^ ((o >> 3) & 0x70);
            }
            #pragma unroll
            for (int nj = 0; nj < 4; nj++) {
                int nrow = wn * 64 + nj * 16 + (lane & 7) + ((lane >> 4) << 3);
                int ko   = kb + (((lane >> 3) & 1) << 4);
                uint32_t o = (uint32_t)(nrow * 128 + ko);
                boff[nj] = o ^ ((o >> 3) & 0x70);
            }

            uint32_t ah[16], bb[16], tt[16];
            #pragma unroll
            for (int mi = 0; mi < 4; mi++)
                ldsm_x4(tAh + aoff[mi], ah[mi*4+0], ah[mi*4+1], ah[mi*4+2], ah[mi*4+3]);
            #pragma unroll
            for (int nj = 0; nj < 4; nj++)
                ldsm_x4(tBh + boff[nj], bb[nj*4+0], bb[nj*4+1], bb[nj*4+2], bb[nj*4+3]);
            #pragma unroll
            for (int mi = 0; mi < 4; mi++)
                #pragma unroll
                for (int ni = 0; ni < 8; ni++)
                    mma_bf16(acc[mi][ni], &ah[mi*4], bb[ni*2], bb[ni*2+1]);
            #pragma unroll
            for (int mi = 0; mi < 4; mi++)
                ldsm_x4(tAl + aoff[mi], tt[mi*4+0], tt[mi*4+1], tt[mi*4+2], tt[mi*4+3]);
            #pragma unroll
            for (int mi = 0; mi < 4; mi++)
                #pragma unroll
                for (int ni = 0; ni < 8; ni++)
                    mma_bf16(acc[mi][ni], &tt[mi*4], bb[ni*2], bb[ni*2+1]);
            #pragma unroll
            for (int nj = 0; nj < 4; nj++)
                ldsm_x4(tBl + boff[nj], tt[nj*4+0], tt[nj*4+1], tt[nj*4+2], tt[nj*4+3]);
            #pragma unroll
            for (int mi = 0; mi < 4; mi++)
                #pragma unroll
                for (int ni = 0; ni < 8; ni++)
                    mma_bf16(acc[mi][ni], &ah[mi*4], tt[ni*2], tt[ni*2+1]);
        }
        __syncthreads();
    }

    #pragma unroll
    for (int mi = 0; mi < 4; mi++) {
        #pragma unroll
        for (int ni = 0; ni < 8; ni++) {
            int row = bm + wm * 64 + mi * 16 + (lane >> 2);
            int col = bn + wn * 64 + ni * 8 + (lane & 3) * 2;
            float2 v0 = make_float2(acc[mi][ni][0], acc[mi][ni][1]);
            float2 v1 = make_float2(acc[mi][ni][2], acc[mi][ni][3]);
            if (EPI == 1) {
                float b0 = __ldg(bias + col), b1 = __ldg(bias + col + 1);
                v0.x = softplus_f(v0.x + b0); v0.y = softplus_f(v0.y + b1);
                v1.x = softplus_f(v1.x + b0); v1.y = softplus_f(v1.y + b1);
            }
            *(float2*)(C + (size_t)row * N + col)       = v0;
            *(float2*)(C + (size_t)(row + 8) * N + col) = v1;
        }
    }
}

// ---------------- prep kernels --------------------------------------------
__global__ __launch_bounds__(256)
void split_h_kernel(const float* __restrict__ in, __half* __restrict__ hi,
                    __half* __restrict__ lo, int n4)
{
    int i = blockIdx.x * 256 + threadIdx.x;
    if (i >= n4) return;
    float4 v = ((const float4*)in)[i];
    ushort4 h, l;
    split1h(v.x, h.x, l.x); split1h(v.y, h.y, l.y);
    split1h(v.z, h.z, l.z); split1h(v.w, h.w, l.w);
    ((ushort4*)hi)[i] = h;
    ((ushort4*)lo)[i] = l;
}

// fp16 transpose (hi only): in [R][C] fp32 -> out [C][R] half
__global__ __launch_bounds__(256)
void trsplit_h_kernel(const float* __restrict__ in, __half* __restrict__ oh,
                      int R, int C)
{
    __shared__ float t[32][33];
    int c0 = blockIdx.x * 32, r0 = blockIdx.y * 32;
    int tx = threadIdx.x, ty = threadIdx.y;
    #pragma unroll
    for (int j = 0; j < 4; j++)
        t[ty + 8 * j][tx] = in[(size_t)(r0 + ty + 8 * j) * C + c0 + tx];
    __syncthreads();
    #pragma unroll
    for (int j = 0; j < 4; j++) {
        float v = t[tx][ty + 8 * j];
        size_t o = (size_t)(c0 + ty + 8 * j) * R + r0 + tx;
        oh[o] = __float2half(v);
    }
}

// bf16 transpose+split: in [R][C] fp32 -> outH/L [C][R] bf16
__global__ __launch_bounds__(256)
void trsplit_kernel(const float* __restrict__ in, __nv_bfloat16* __restrict__ oh,
                    __nv_bfloat16* __restrict__ ol, int R, int C)
{
    __shared__ float t[32][33];
    int c0 = blockIdx.x * 32, r0 = blockIdx.y * 32;
    int tx = threadIdx.x, ty = threadIdx.y;
    #pragma unroll
    for (int j = 0; j < 4; j++)
        t[ty + 8 * j][tx] = in[(size_t)(r0 + ty + 8 * j) * C + c0 + tx];
    __syncthreads();
    #pragma unroll
    for (int j = 0; j < 4; j++) {
        float v = t[tx][ty + 8 * j];
        unsigned short h, l; split1(v, h, l);
        size_t o = (size_t)(c0 + ty + 8 * j) * R + r0 + tx;
        *(unsigned short*)(oh + o) = h;
        *(unsigned short*)(ol + o) = l;
    }
}

// reduce split-K partials -> xdbl (padded) + fused dt_in bf16 split
__global__ __launch_bounds__(256)
void xdbl_reduce_kernel(const float* __restrict__ part, float* __restrict__ xdbl,
                        __nv_bfloat16* __restrict__ dih, __nv_bfloat16* __restrict__ dil)
{
    int i = blockIdx.x * 256 + threadIdx.x;
    if (i >= TT * (XPAD / 4)) return;
    float4 s = make_float4(0.f, 0.f, 0.f, 0.f);
    #pragma unroll
    for (int z = 0; z < NSPLITK; z++) {
        float4 v = ((const float4*)(part + (size_t)z * TT * XPAD))[i];
        s.x += v.x; s.y += v.y; s.z += v.z; s.w += v.w;
    }
    ((float4*)xdbl)[i] = s;
    int col = (i & (XPAD/4 - 1)) * 4;
    if (col < RR) {
        int row = i / (XPAD/4);
        ushort4 h, l;
        split1(s.x, h.x, l.x); split1(s.y, h.y, l.y);
        split1(s.z, h.z, l.z); split1(s.w, h.w, l.w);
        size_t o = ((size_t)row * RR + col) >> 2;
        ((ushort4*)dih)[o] = h;
        ((ushort4*)dil)[o] = l;
    }
}

// ---------------- depthwise conv3 + bias + SiLU (+ bf16 split out) --------
__global__ __launch_bounds__(256)
void conv_silu_kernel(const float* __restrict__ xz, const float* __restrict__ w,
                      const float* __restrict__ bias, float* __restrict__ xc,
                      __nv_bfloat16* __restrict__ xch, __nv_bfloat16* __restrict__ xcl)
{
    int i = blockIdx.x * blockDim.x + threadIdx.x;
    const int NW = TT * (DD/4);
    if (i >= NW) return;
    int c4 = i % (DD/4);
    int t  = i / (DD/4);
    int l  = t & (LL - 1);
    int c  = c4 * 4;

    const float* p = xz + (size_t)t * (2*DD) + c;
    float4 x0 = *(const float4*)p;
    float4 xm = (l > 0)      ? *(const float4*)(p - 2*DD) : make_float4(0,0,0,0);
    float4 xp = (l < LL - 1) ? *(const float4*)(p + 2*DD) : make_float4(0,0,0,0);

    float xmv[4] = {xm.x, xm.y, xm.z, xm.w};
    float x0v[4] = {x0.x, x0.y, x0.z, x0.w};
    float xpv[4] = {xp.x, xp.y, xp.z, xp.w};
    float out[4];
    #pragma unroll
    for (int j = 0; j < 4; j++) {
        int cc = c + j;
        float v = xmv[j]*w[cc*3+0] + x0v[j]*w[cc*3+1] + xpv[j]*w[cc*3+2] + bias[cc];
        out[j] = silu_f(v);
    }
    *(float4*)(xc + (size_t)t*DD + c) = make_float4(out[0], out[1], out[2], out[3]);
    ushort4 h, l4;
    split1(out[0], h.x, l4.x); split1(out[1], h.y, l4.y);
    split1(out[2], h.z, l4.z); split1(out[3], h.w, l4.w);
    size_t o = ((size_t)t*DD + c) >> 2;
    ((ushort4*)xch)[o] = h;
    ((ushort4*)xcl)[o] = l4;
}

// ---------------- selective scan + fused gated mix ------------------------
#define SCH 32
#define SNC (LL / SCH)
#define SCAN_SMEM ((24576 + 2048) * 4)

__global__ __launch_bounds__(128)
void scan_kernel(const float* __restrict__ xc, const float* __restrict__ dt,
                 const float* __restrict__ xdbl, const float* __restrict__ A_log,
                 const float* __restrict__ xz, const float* __restrict__ Dp,
                 __half* __restrict__ yh, __half* __restrict__ yl)
{
    extern __shared__ float sm[];
    float* sU  = sm;
    float* sDT = sm + 8192;
    float* sZ  = sm + 16384;
    float* sBC = sm + 24576;

    const int tid = threadIdx.x;
    const int c0  = blockIdx.x * 128;
    const int c   = c0 + tid;
    const int b   = blockIdx.y;

    float eps[SSTATE];
    #pragma unroll
    for (int s = 0; s < SSTATE; s++)
        eps[s] = (float)(s + 1) - expf(A_log[(size_t)c*SSTATE + s]);
    const float Dv = Dp[c];

    float h[SSTATE];
    #pragma unroll
    for (int s = 0; s < SSTATE; s++) h[s] = 0.0f;

    const float* xcrow = xc   + (size_t)b * LL * DD + c0;
    const float* dtrow = dt   + (size_t)b * LL * DD + c0;
    const float* zrow  = xz   + (size_t)b * LL * (2*DD) + DD + c0;
    const float* bcrow = xdbl + (size_t)b * LL * XPAD + RR;

    const uint32_t sb = smem_u32(sm);
    auto load_chunk = [&](int lc, int buf) {
        const int l0 = lc * SCH;
        #pragma unroll
        for (int k = 0; k < 8; k++) {
            int idx = k * 128 + tid;
            int r = idx >> 5, q = idx & 31;
            uint32_t so = (uint32_t)(((buf * SCH + r) * 128 + q * 4) * 4);
            cp_async16(sb + so,           xcrow + (size_t)(l0 + r) * DD     + q * 4);
            cp_async16(sb + 32768 + so,   dtrow + (size_t)(l0 + r) * DD     + q * 4);
            cp_async16(sb + 65536 + so,   zrow  + (size_t)(l0 + r) * (2*DD) + q * 4);
        }
        #pragma unroll
        for (int k = 0; k < 2; k++) {
            int idx = k * 128 + tid;
            int r = idx >> 3, q = idx & 7;
            uint32_t so = (uint32_t)(98304 + ((buf * SCH + r) * 32 + q * 4) * 4);
            cp_async16(sb + so, bcrow + (size_t)(l0 + r) * XPAD + q * 4);
        }
        asm volatile("cp.async.commit_group;" ::: "memory");
    };

    load_chunk(0, 0);

    for (int lc = 0; lc < SNC; lc++) {
        const int buf = lc & 1;
        if (lc + 1 < SNC) {
            load_chunk(lc + 1, 1 - buf);
            asm volatile("cp.async.wait_group 1;" ::: "memory");
        } else {
            asm volatile("cp.async.wait_group 0;" ::: "memory");
        }
        __syncthreads();

        #pragma unroll 4
        for (int ll = 0; ll < SCH; ll++) {
            const int l = lc * SCH + ll;
            const int ro = (buf * SCH + ll);
            float u   = sU [ro * 128 + tid];
            float dtv = sDT[ro * 128 + tid];
            float zv  = sZ [ro * 128 + tid];
            const float4* bc = (const float4*)&sBC[ro * 32];
            float4 q0 = bc[0], q1 = bc[1], q2 = bc[2], q3 = bc[3];
            float4 q4 = bc[4], q5 = bc[5], q6 = bc[6], q7 = bc[7];
            float Bv[SSTATE] = {q0.x,q0.y,q0.z,q0.w, q1.x,q1.y,q1.z,q1.w,
                                q2.x,q2.y,q2.z,q2.w, q3.x,q3.y,q3.z,q3.w};
            float Cv[SSTATE] = {q4.x,q4.y,q4.z,q4.w, q5.x,q5.y,q5.z,q5.w,
                                q6.x,q6.y,q6.z,q6.w, q7.x,q7.y,q7.z,q7.w};

            float p1  = __expf(-dtv);
            float p2  = p1*p1;
            float p4  = p2*p2;
            float p8  = p4*p4;
            float p16 = p8*p8;
            float du  = dtv * u;

            float y0 = 0.f, y1 = 0.f, y2 = 0.f, y3 = 0.f;
            #pragma unroll
            for (int s = 0; s < SSTATE; s++) {
                const int e = s + 1;
                float pw = 1.0f;
                if (e & 1)  pw *= p1;
                if (e & 2)  pw *= p2;
                if (e & 4)  pw *= p4;
                if (e & 8)  pw *= p8;
                if (e & 16) pw *= p16;
                float dA = pw * fmaf(eps[s], dtv, 1.0f);
                h[s] = fmaf(dA, h[s], du * Bv[s]);
                float t2 = h[s] * Cv[s];
                if      ((s & 3) == 0) y0 += t2;
                else if ((s & 3) == 1) y1 += t2;
                else if ((s & 3) == 2) y2 += t2;
                else                   y3 += t2;
            }
            float ys = (y0 + y1) + (y2 + y3);
            float o  = fmaf(u, Dv, ys) * silu_f(zv);
            unsigned short oh, ol;
            split1h(o, oh, ol);
            size_t oidx = (size_t)b * LL * DD + (size_t)l * DD + c;
            *(unsigned short*)(yh + oidx) = oh;
            *(unsigned short*)(yl + oidx) = ol;
        }
        __syncthreads();
    }
}

// ---------------- launch ---------------------------------------------------
extern "C" void kernel_launch(void* const* d_in, const int* in_sizes, int n_in,
                              void* d_out, int out_size)
{
    const float* x      = (const float*)d_in[0];
    const float* W_in   = (const float*)d_in[1];
    const float* conv_w = (const float*)d_in[2];
    const float* conv_b = (const float*)d_in[3];
    const float* W_x    = (const float*)d_in[4];
    const float* W_dt   = (const float*)d_in[5];
    const float* b_dt   = (const float*)d_in[6];
    const float* A_log  = (const float*)d_in[7];
    const float* D      = (const float*)d_in[8];
    const float* W_out  = (const float*)d_in[9];
    float* out = (float*)d_out;

    float *xz, *xc, *xdbl, *xpart, *dtb;
    __half *xh, *xl, *wih, *woh, *yh, *yl;
    __nv_bfloat16 *wdh, *wdl, *wxh, *wxl, *xch, *xcl, *dih, *dil;
    cudaGetSymbolAddress((void**)&xz,    g_xz);
    cudaGetSymbolAddress((void**)&xc,    g_xc);
    cudaGetSymbolAddress((void**)&xdbl,  g_xdbl);
    cudaGetSymbolAddress((void**)&xpart, g_xpart);
    cudaGetSymbolAddress((void**)&dtb,   g_dt);
    cudaGetSymbolAddress((void**)&xh,  g_xh);  cudaGetSymbolAddress((void**)&xl,  g_xl);
    cudaGetSymbolAddress((void**)&wih, g_wih);
    cudaGetSymbolAddress((void**)&woh, g_woh);
    cudaGetSymbolAddress((void**)&wdh, g_wdh); cudaGetSymbolAddress((void**)&wdl, g_wdl);
    cudaGetSymbolAddress((void**)&wxh, g_wxh); cudaGetSymbolAddress((void**)&wxl, g_wxl);
    cudaGetSymbolAddress((void**)&xch, g_xch); cudaGetSymbolAddress((void**)&xcl, g_xcl);
    cudaGetSymbolAddress((void**)&dih, g_dih); cudaGetSymbolAddress((void**)&dil, g_dil);
    cudaGetSymbolAddress((void**)&yh,  g_yh);  cudaGetSymbolAddress((void**)&yl,  g_yl);

    cudaFuncSetAttribute(mma_gemm128h,   cudaFuncAttributeMaxDynamicSharedMemorySize, H_SMEM);
    cudaFuncSetAttribute(mma_gemm256<0>, cudaFuncAttributeMaxDynamicSharedMemorySize, G_SMEM);
    cudaFuncSetAttribute(mma_gemm256<1>, cudaFuncAttributeMaxDynamicSharedMemorySize, G_SMEM);
    cudaFuncSetAttribute(scan_kernel,    cudaFuncAttributeMaxDynamicSharedMemorySize, SCAN_SMEM);

    // idx0: split x -> fp16 hi/lo
    split_h_kernel<<<(TT*HH/4 + 255)/256, 256>>>(x, xh, xl, TT*HH/4);
    // idx1: W_in^T -> fp16 hi
    trsplit_h_kernel<<<dim3(2*DD/32, HH/32), dim3(32,8)>>>(W_in, wih, HH, 2*DD);
    // idx2: W_out^T -> fp16 hi
    trsplit_h_kernel<<<dim3(HH/32, DD/32), dim3(32,8)>>>(W_out, woh, DD, HH);
    // idx3: GEMM1 (ncu capture slot): xz = x @ W_in  (2048 x 8192, K=2048), fp16 2-pass
    mma_gemm128h<<<dim3(2*DD/128, TT/128), 256, H_SMEM>>>(
        xh, xl, wih, xz, TT, 2*DD, HH, HH);
    // idx4: W_dt^T split (bf16)
    trsplit_kernel<<<dim3(DD/32,  RR/32),  dim3(32,8)>>>(W_dt,  wdh, wdl, RR,  DD);
    // idx5: W_x^T split (bf16, padded)
    trsplit_kernel<<<dim3(XDBL_N/32, DD/32), dim3(32,8)>>>(W_x, wxh, wxl, DD, XDBL_N);
    // idx6: conv + silu -> xc + bf16 split
    conv_silu_kernel<<<(TT*(DD/4) + 255)/256, 256>>>(xz, conv_w, conv_b, xc, xch, xcl);
    // idx7: x_dbl split-K (bf16 3-pass)
    mma_gemm256<0><<<dim3(XPAD/128, TT/256, NSPLITK), 256, G_SMEM>>>(
        xch, xcl, wxh, wxl, xpart, TT, XPAD, DD, DD/NSPLITK, nullptr);
    // idx8: reduce + dt_in split
    xdbl_reduce_kernel<<<(TT*(XPAD/4) + 255)/256, 256>>>(xpart, xdbl, dih, dil);
    // idx9: dt GEMM + softplus (bf16 3-pass)
    mma_gemm256<1><<<dim3(DD/128, TT/256), 256, G_SMEM>>>(
        dih, dil, wdh, wdl, dtb, TT, DD, RR, RR, b_dt);
    // idx10: scan + fused mix -> yh/yl (fp16)
    scan_kernel<<<dim3(DD/128, BBATCH), 128, SCAN_SMEM>>>(
        xc, dtb, xdbl, A_log, xz, D, yh, yl);
    // idx11: out = y @ W_out  (2048 x 2048, K=4096), fp16 2-pass
    mma_gemm128h<<<dim3(HH/128, TT/128), 256, H_SMEM>>>(
        yh, yl, woh, out, TT, HH, DD, DD);
}

// round 14
// speedup vs baseline: 1.8994x; 1.0295x over previous
#include <cuda_runtime.h>
#include <cuda_fp16.h>
#include <math.h>
#include <stdint.h>

// Problem dims (fixed)
#define BBATCH 2
#define LL   1024
#define HH   2048
#define DD   4096      // d = H*E
#define SSTATE 16
#define RR   128
#define TT   2048      // B*L tokens
#define XDBL_N 160     // R + 2S
#define XPAD 256       // padded x_dbl width
#define NSPLITK 8

// ---------------- scratch (static device globals; no allocation) ----------
__device__ float g_xz  [(size_t)TT * 2 * DD];
__device__ float g_xc  [(size_t)TT * DD];
__device__ float g_xdbl[(size_t)TT * XPAD];                 // padded
__device__ float g_xpart[(size_t)NSPLITK * TT * XPAD];      // split-K partials
__device__ float g_dt  [(size_t)TT * DD];

// fp16 split operands
__device__ __half g_xh [(size_t)TT * HH];
__device__ __half g_xl [(size_t)TT * HH];
__device__ __half g_wih[(size_t)2 * DD * HH];   // W_in^T  [8192][2048] (hi only)
__device__ __half g_woh[(size_t)HH * DD];       // W_out^T [2048][4096] (hi only)
__device__ __half g_yh [(size_t)TT * DD];
__device__ __half g_yl [(size_t)TT * DD];
__device__ __half g_wdh[(size_t)DD * RR];       // W_dt^T  [4096][128] hi
__device__ __half g_wdl[(size_t)DD * RR];       //                     lo
__device__ __half g_wxh[(size_t)XPAD * DD];     // W_x^T [256pad][4096] hi (rows 160+ zero)
__device__ __half g_wxl[(size_t)XPAD * DD];
__device__ __half g_xch[(size_t)TT * DD];       // split of xc
__device__ __half g_xcl[(size_t)TT * DD];
__device__ __half g_dih[(size_t)TT * RR];       // dt_in [2048][128]
__device__ __half g_dil[(size_t)TT * RR];

// ---------------- small helpers ------------------------------------------
__device__ __forceinline__ float silu_f(float x) { return x / (1.0f + __expf(-x)); }
__device__ __forceinline__ float softplus_f(float x) {
    return fmaxf(x, 0.0f) + log1pf(__expf(-fabsf(x)));
}
__device__ __forceinline__ uint32_t smem_u32(const void* p) {
    uint32_t a;
    asm("{ .reg .u64 t; cvta.to.shared.u64 t, %1; cvt.u32.u64 %0, t; }" : "=r"(a) : "l"(p));
    return a;
}
__device__ __forceinline__ unsigned short h_bits(__half h) {
    unsigned short u; *(__half*)&u = h; return u;
}
__device__ __forceinline__ void split1h(float v, unsigned short& h, unsigned short& l) {
    __half hb = __float2half(v);
    __half lb = __float2half(v - __half2float(hb));
    h = h_bits(hb); l = h_bits(lb);
}
__device__ __forceinline__ void cp_async16(uint32_t dst, const void* src) {
    asm volatile("cp.async.cg.shared.global [%0], [%1], 16;" :: "r"(dst), "l"(src));
}
__device__ __forceinline__ void ldsm_x4(uint32_t addr, uint32_t& r0, uint32_t& r1,
                                        uint32_t& r2, uint32_t& r3) {
    asm volatile("ldmatrix.sync.aligned.m8n8.x4.shared.b16 {%0,%1,%2,%3}, [%4];"
                 : "=r"(r0), "=r"(r1), "=r"(r2), "=r"(r3) : "r"(addr));
}
__device__ __forceinline__ void mma_f16(float* c, const uint32_t* a,
                                        uint32_t b0, uint32_t b1) {
    asm volatile(
        "mma.sync.aligned.m16n8k16.row.col.f32.f16.f16.f32 "
        "{%0,%1,%2,%3}, {%4,%5,%6,%7}, {%8,%9}, {%0,%1,%2,%3};"
        : "+f"(c[0]), "+f"(c[1]), "+f"(c[2]), "+f"(c[3])
        : "r"(a[0]), "r"(a[1]), "r"(a[2]), "r"(a[3]), "r"(b0), "r"(b1));
}

// ======== fp16 GEMM: 128x128 tile, templated passes ========================
// C[M,N] (+= split-K plane) = (Ah+Al) @ Bh^T   [+ Ah @ Bl^T if THIRD]
// BK=64, 2-stage cp.async, 256 threads, warp tile 32x64.
// EPI: 0 plain, 1 = +bias then softplus.
#define H_AT 16384

template<int EPI, bool THIRD>
__global__ __launch_bounds__(256, THIRD ? 1 : 2)
void mma_gemm128h(const __half* __restrict__ Ah, const __half* __restrict__ Al,
                  const __half* __restrict__ Bh, const __half* __restrict__ Bl,
                  float* __restrict__ C, int M, int N, int ldk, int kLen,
                  const float* __restrict__ bias)
{
    constexpr uint32_t STAGE = (THIRD ? 4 : 3) * H_AT;
    extern __shared__ char smem_raw[];
    const uint32_t sb = (smem_u32(smem_raw) + 1023u) & ~1023u;

    const int tid  = threadIdx.x;
    const int lane = tid & 31;
    const int wid  = tid >> 5;
    const int wm   = wid & 3;        // 4 m-slabs of 32
    const int wn   = wid >> 2;       // 2 n-slabs of 64
    const int bm = blockIdx.y * 128;
    const int bn = blockIdx.x * 128;
    const int kOff = blockIdx.z * kLen;
    C += (size_t)blockIdx.z * (size_t)M * (size_t)N;

    uint32_t sw[4]; uint32_t gofs[4];
    #pragma unroll
    for (int i = 0; i < 4; i++) {
        int c = i * 256 + tid;
        int row = c >> 3, kb = c & 7;
        uint32_t o = (uint32_t)(row * 128 + kb * 16);
        sw[i]   = o ^ ((o >> 3) & 0x70);
        gofs[i] = (uint32_t)(row * ldk * 2 + kb * 16);
    }
    const char* srcAh = (const char*)(Ah + (size_t)bm * ldk + kOff);
    const char* srcAl = (const char*)(Al + (size_t)bm * ldk + kOff);
    const char* srcBh = (const char*)(Bh + (size_t)bn * ldk + kOff);
    const char* srcBl = THIRD ? (const char*)(Bl + (size_t)bn * ldk + kOff) : nullptr;

    float acc[2][8][4];
    #pragma unroll
    for (int mi = 0; mi < 2; mi++)
        #pragma unroll
        for (int ni = 0; ni < 8; ni++)
            #pragma unroll
            for (int r = 0; r < 4; r++) acc[mi][ni][r] = 0.0f;

    const int NK = kLen >> 6;

    auto load_stage = [&](int kblk, int s) {
        uint32_t base = sb + (uint32_t)s * STAGE;
        uint32_t kadd = (uint32_t)kblk * 128;
        #pragma unroll
        for (int i = 0; i < 4; i++) cp_async16(base + sw[i],            srcAh + kadd + gofs[i]);
        #pragma unroll
        for (int i = 0; i < 4; i++) cp_async16(base + H_AT + sw[i],     srcAl + kadd + gofs[i]);
        #pragma unroll
        for (int i = 0; i < 4; i++) cp_async16(base + 2*H_AT + sw[i],   srcBh + kadd + gofs[i]);
        if (THIRD) {
            #pragma unroll
            for (int i = 0; i < 4; i++) cp_async16(base + 3*H_AT + sw[i], srcBl + kadd + gofs[i]);
        }
        asm volatile("cp.async.commit_group;" ::: "memory");
    };

    load_stage(0, 0);

    for (int kblk = 0; kblk < NK; kblk++) {
        int s = kblk & 1;
        if (kblk + 1 < NK) {
            load_stage(kblk + 1, 1 - s);
            asm volatile("cp.async.wait_group 1;" ::: "memory");
        } else {
            asm volatile("cp.async.wait_group 0;" ::: "memory");
        }
        __syncthreads();

        uint32_t base = sb + (uint32_t)s * STAGE;
        uint32_t tAh = base, tAl = base + H_AT, tBh = base + 2*H_AT;
        uint32_t tBl = base + 3*H_AT;

        #pragma unroll
        for (int kk = 0; kk < 4; kk++) {
            const int kb = kk * 32;
            uint32_t aoff[2], boff[4];
            #pragma unroll
            for (int mi = 0; mi < 2; mi++) {
                int mrow = wm * 32 + mi * 16 + (lane & 15);
                int ko   = kb + ((lane >> 4) << 4);
                uint32_t o = (uint32_t)(mrow * 128 + ko);
                aoff[mi] = o ^ ((o >> 3) & 0x70);
            }
            #pragma unroll
            for (int nj = 0; nj < 4; nj++) {
                int nrow = wn * 64 + nj * 16 + (lane & 7) + ((lane >> 4) << 3);
                int ko   = kb + (((lane >> 3) & 1) << 4);
                uint32_t o = (uint32_t)(nrow * 128 + ko);
                boff[nj] = o ^ ((o >> 3) & 0x70);
            }

            uint32_t ah[8], bb[16], tt[8];
            #pragma unroll
            for (int mi = 0; mi < 2; mi++)
                ldsm_x4(tAh + aoff[mi], ah[mi*4+0], ah[mi*4+1], ah[mi*4+2], ah[mi*4+3]);
            #pragma unroll
            for (int nj = 0; nj < 4; nj++)
                ldsm_x4(tBh + boff[nj], bb[nj*4+0], bb[nj*4+1], bb[nj*4+2], bb[nj*4+3]);
            // pass 0: ah * bh
            #pragma unroll
            for (int mi = 0; mi < 2; mi++)
                #pragma unroll
                for (int ni = 0; ni < 8; ni++)
                    mma_f16(acc[mi][ni], &ah[mi*4], bb[ni*2], bb[ni*2+1]);
            // pass 1: al * bh
            #pragma unroll
            for (int mi = 0; mi < 2; mi++)
                ldsm_x4(tAl + aoff[mi], tt[mi*4+0], tt[mi*4+1], tt[mi*4+2], tt[mi*4+3]);
            #pragma unroll
            for (int mi = 0; mi < 2; mi++)
                #pragma unroll
                for (int ni = 0; ni < 8; ni++)
                    mma_f16(acc[mi][ni], &tt[mi*4], bb[ni*2], bb[ni*2+1]);
            if (THIRD) {
                // pass 2: ah * bl (reuse bb for bl)
                #pragma unroll
                for (int nj = 0; nj < 4; nj++)
                    ldsm_x4(tBl + boff[nj], bb[nj*4+0], bb[nj*4+1], bb[nj*4+2], bb[nj*4+3]);
                #pragma unroll
                for (int mi = 0; mi < 2; mi++)
                    #pragma unroll
                    for (int ni = 0; ni < 8; ni++)
                        mma_f16(acc[mi][ni], &ah[mi*4], bb[ni*2], bb[ni*2+1]);
            }
        }
        __syncthreads();
    }

    #pragma unroll
    for (int mi = 0; mi < 2; mi++) {
        #pragma unroll
        for (int ni = 0; ni < 8; ni++) {
            int row = bm + wm * 32 + mi * 16 + (lane >> 2);
            int col = bn + wn * 64 + ni * 8 + (lane & 3) * 2;
            float2 v0 = make_float2(acc[mi][ni][0], acc[mi][ni][1]);
            float2 v1 = make_float2(acc[mi][ni][2], acc[mi][ni][3]);
            if (EPI == 1) {
                float b0 = __ldg(bias + col), b1 = __ldg(bias + col + 1);
                v0.x = softplus_f(v0.x + b0); v0.y = softplus_f(v0.y + b1);
                v1.x = softplus_f(v1.x + b0); v1.y = softplus_f(v1.y + b1);
            }
            *(float2*)(C + (size_t)row * N + col)       = v0;
            *(float2*)(C + (size_t)(row + 8) * N + col) = v1;
        }
    }
}

#define H_SMEM2 (2 * 3 * H_AT + 1024)
#define H_SMEM3 (2 * 4 * H_AT + 1024)

// ---------------- prep kernels --------------------------------------------
__global__ __launch_bounds__(256)
void split_h_kernel(const float* __restrict__ in, __half* __restrict__ hi,
                    __half* __restrict__ lo, int n4)
{
    int i = blockIdx.x * 256 + threadIdx.x;
    if (i >= n4) return;
    float4 v = ((const float4*)in)[i];
    ushort4 h, l;
    split1h(v.x, h.x, l.x); split1h(v.y, h.y, l.y);
    split1h(v.z, h.z, l.z); split1h(v.w, h.w, l.w);
    ((ushort4*)hi)[i] = h;
    ((ushort4*)lo)[i] = l;
}

// fast 64x64 transpose, hi only: in [R][C] fp32 -> out [C][R] half
__global__ __launch_bounds__(256)
void trsplit_h64(const float* __restrict__ in, __half* __restrict__ oh, int R, int C)
{
    __shared__ float t[64][65];
    int c0 = blockIdx.x * 64, r0 = blockIdx.y * 64;
    int tid = threadIdx.x;
    #pragma unroll
    for (int k = 0; k < 4; k++) {
        int idx = k * 256 + tid;
        int row = idx >> 4, c4 = idx & 15;
        float4 v = *(const float4*)(in + (size_t)(r0 + row) * C + c0 + c4 * 4);
        t[row][c4*4+0] = v.x; t[row][c4*4+1] = v.y;
        t[row][c4*4+2] = v.z; t[row][c4*4+3] = v.w;
    }
    __syncthreads();
    #pragma unroll
    for (int k = 0; k < 4; k++) {
        int idx = k * 256 + tid;
        int cc = idx >> 4, rq = idx & 15;
        int rr = rq * 4;
        ushort4 h;
        h.x = h_bits(__float2half(t[rr+0][cc]));
        h.y = h_bits(__float2half(t[rr+1][cc]));
        h.z = h_bits(__float2half(t[rr+2][cc]));
        h.w = h_bits(__float2half(t[rr+3][cc]));
        *(ushort4*)(oh + (size_t)(c0 + cc) * R + r0 + rr) = h;
    }
}

// fast 64x64 transpose, hi+lo
__global__ __launch_bounds__(256)
void trsplit_h2_64(const float* __restrict__ in, __half* __restrict__ oh,
                   __half* __restrict__ ol, int R, int C)
{
    __shared__ float t[64][65];
    int c0 = blockIdx.x * 64, r0 = blockIdx.y * 64;
    int tid = threadIdx.x;
    #pragma unroll
    for (int k = 0; k < 4; k++) {
        int idx = k * 256 + tid;
        int row = idx >> 4, c4 = idx & 15;
        float4 v = *(const float4*)(in + (size_t)(r0 + row) * C + c0 + c4 * 4);
        t[row][c4*4+0] = v.x; t[row][c4*4+1] = v.y;
        t[row][c4*4+2] = v.z; t[row][c4*4+3] = v.w;
    }
    __syncthreads();
    #pragma unroll
    for (int k = 0; k < 4; k++) {
        int idx = k * 256 + tid;
        int cc = idx >> 4, rq = idx & 15;
        int rr = rq * 4;
        ushort4 h, l;
        split1h(t[rr+0][cc], h.x, l.x);
        split1h(t[rr+1][cc], h.y, l.y);
        split1h(t[rr+2][cc], h.z, l.z);
        split1h(t[rr+3][cc], h.w, l.w);
        size_t o = ((size_t)(c0 + cc) * R + r0 + rr);
        *(ushort4*)(oh + o) = h;
        *(ushort4*)(ol + o) = l;
    }
}

// 32-wide transpose hi+lo (for W_x: C=160)
__global__ __launch_bounds__(256)
void trsplit_h2_32(const float* __restrict__ in, __half* __restrict__ oh,
                   __half* __restrict__ ol, int R, int C)
{
    __shared__ float t[32][33];
    int c0 = blockIdx.x * 32, r0 = blockIdx.y * 32;
    int tx = threadIdx.x & 31, ty = threadIdx.x >> 5;
    #pragma unroll
    for (int j = 0; j < 4; j++)
        t[ty + 8 * j][tx] = in[(size_t)(r0 + ty + 8 * j) * C + c0 + tx];
    __syncthreads();
    #pragma unroll
    for (int j = 0; j < 4; j++) {
        float v = t[tx][ty + 8 * j];
        unsigned short h, l; split1h(v, h, l);
        size_t o = (size_t)(c0 + ty + 8 * j) * R + r0 + tx;
        *(unsigned short*)(oh + o) = h;
        *(unsigned short*)(ol + o) = l;
    }
}

// reduce split-K partials -> xdbl (padded) + fused dt_in fp16 split
__global__ __launch_bounds__(256)
void xdbl_reduce_kernel(const float* __restrict__ part, float* __restrict__ xdbl,
                        __half* __restrict__ dih, __half* __restrict__ dil)
{
    int i = blockIdx.x * 256 + threadIdx.x;
    if (i >= TT * (XPAD / 4)) return;
    float4 s = make_float4(0.f, 0.f, 0.f, 0.f);
    #pragma unroll
    for (int z = 0; z < NSPLITK; z++) {
        float4 v = ((const float4*)(part + (size_t)z * TT * XPAD))[i];
        s.x += v.x; s.y += v.y; s.z += v.z; s.w += v.w;
    }
    ((float4*)xdbl)[i] = s;
    int col = (i & (XPAD/4 - 1)) * 4;
    if (col < RR) {
        int row = i / (XPAD/4);
        ushort4 h, l;
        split1h(s.x, h.x, l.x); split1h(s.y, h.y, l.y);
        split1h(s.z, h.z, l.z); split1h(s.w, h.w, l.w);
        size_t o = ((size_t)row * RR + col) >> 2;
        ((ushort4*)dih)[o] = h;
        ((ushort4*)dil)[o] = l;
    }
}

// ---------------- depthwise conv3 + bias + SiLU (+ fp16 split out) --------
__global__ __launch_bounds__(256)
void conv_silu_kernel(const float* __restrict__ xz, const float* __restrict__ w,
                      const float* __restrict__ bias, float* __restrict__ xc,
                      __half* __restrict__ xch, __half* __restrict__ xcl)
{
    int i = blockIdx.x * blockDim.x + threadIdx.x;
    const int NW = TT * (DD/4);
    if (i >= NW) return;
    int c4 = i % (DD/4);
    int t  = i / (DD/4);
    int l  = t & (LL - 1);
    int c  = c4 * 4;

    const float* p = xz + (size_t)t * (2*DD) + c;
    float4 x0 = *(const float4*)p;
    float4 xm = (l > 0)      ? *(const float4*)(p - 2*DD) : make_float4(0,0,0,0);
    float4 xp = (l < LL - 1) ? *(const float4*)(p + 2*DD) : make_float4(0,0,0,0);

    float xmv[4] = {xm.x, xm.y, xm.z, xm.w};
    float x0v[4] = {x0.x, x0.y, x0.z, x0.w};
    float xpv[4] = {xp.x, xp.y, xp.z, xp.w};
    float out[4];
    #pragma unroll
    for (int j = 0; j < 4; j++) {
        int cc = c + j;
        float v = xmv[j]*w[cc*3+0] + x0v[j]*w[cc*3+1] + xpv[j]*w[cc*3+2] + bias[cc];
        out[j] = silu_f(v);
    }
    *(float4*)(xc + (size_t)t*DD + c) = make_float4(out[0], out[1], out[2], out[3]);
    ushort4 h, l4;
    split1h(out[0], h.x, l4.x); split1h(out[1], h.y, l4.y);
    split1h(out[2], h.z, l4.z); split1h(out[3], h.w, l4.w);
    size_t o = ((size_t)t*DD + c) >> 2;
    ((ushort4*)xch)[o] = h;
    ((ushort4*)xcl)[o] = l4;
}

// ---------------- selective scan + fused gated mix ------------------------
#define SCH 32
#define SNC (LL / SCH)
#define SCAN_SMEM ((24576 + 2048) * 4)

__global__ __launch_bounds__(128)
void scan_kernel(const float* __restrict__ xc, const float* __restrict__ dt,
                 const float* __restrict__ xdbl, const float* __restrict__ A_log,
                 const float* __restrict__ xz, const float* __restrict__ Dp,
                 __half* __restrict__ yh, __half* __restrict__ yl)
{
    extern __shared__ float sm[];
    float* sU  = sm;
    float* sDT = sm + 8192;
    float* sZ  = sm + 16384;
    float* sBC = sm + 24576;

    const int tid = threadIdx.x;
    const int c0  = blockIdx.x * 128;
    const int c   = c0 + tid;
    const int b   = blockIdx.y;

    float eps[SSTATE];
    #pragma unroll
    for (int s = 0; s < SSTATE; s++)
        eps[s] = (float)(s + 1) - expf(A_log[(size_t)c*SSTATE + s]);
    const float Dv = Dp[c];

    float h[SSTATE];
    #pragma unroll
    for (int s = 0; s < SSTATE; s++) h[s] = 0.0f;

    const float* xcrow = xc   + (size_t)b * LL * DD + c0;
    const float* dtrow = dt   + (size_t)b * LL * DD + c0;
    const float* zrow  = xz   + (size_t)b * LL * (2*DD) + DD + c0;
    const float* bcrow = xdbl + (size_t)b * LL * XPAD + RR;

    const uint32_t sb = smem_u32(sm);
    auto load_chunk = [&](int lc, int buf) {
        const int l0 = lc * SCH;
        #pragma unroll
        for (int k = 0; k < 8; k++) {
            int idx = k * 128 + tid;
            int r = idx >> 5, q = idx & 31;
            uint32_t so = (uint32_t)(((buf * SCH + r) * 128 + q * 4) * 4);
            cp_async16(sb + so,           xcrow + (size_t)(l0 + r) * DD     + q * 4);
            cp_async16(sb + 32768 + so,   dtrow + (size_t)(l0 + r) * DD     + q * 4);
            cp_async16(sb + 65536 + so,   zrow  + (size_t)(l0 + r) * (2*DD) + q * 4);
        }
        #pragma unroll
        for (int k = 0; k < 2; k++) {
            int idx = k * 128 + tid;
            int r = idx >> 3, q = idx & 7;
            uint32_t so = (uint32_t)(98304 + ((buf * SCH + r) * 32 + q * 4) * 4);
            cp_async16(sb + so, bcrow + (size_t)(l0 + r) * XPAD + q * 4);
        }
        asm volatile("cp.async.commit_group;" ::: "memory");
    };

    load_chunk(0, 0);

    for (int lc = 0; lc < SNC; lc++) {
        const int buf = lc & 1;
        if (lc + 1 < SNC) {
            load_chunk(lc + 1, 1 - buf);
            asm volatile("cp.async.wait_group 1;" ::: "memory");
        } else {
            asm volatile("cp.async.wait_group 0;" ::: "memory");
        }
        __syncthreads();

        #pragma unroll 4
        for (int ll = 0; ll < SCH; ll++) {
            const int l = lc * SCH + ll;
            const int ro = (buf * SCH + ll);
            float u   = sU [ro * 128 + tid];
            float dtv = sDT[ro * 128 + tid];
            float zv  = sZ [ro * 128 + tid];
            const float4* bc = (const float4*)&sBC[ro * 32];
            float4 q0 = bc[0], q1 = bc[1], q2 = bc[2], q3 = bc[3];
            float4 q4 = bc[4], q5 = bc[5], q6 = bc[6], q7 = bc[7];
            float Bv[SSTATE] = {q0.x,q0.y,q0.z,q0.w, q1.x,q1.y,q1.z,q1.w,
                                q2.x,q2.y,q2.z,q2.w, q3.x,q3.y,q3.z,q3.w};
            float Cv[SSTATE] = {q4.x,q4.y,q4.z,q4.w, q5.x,q5.y,q5.z,q5.w,
                                q6.x,q6.y,q6.z,q6.w, q7.x,q7.y,q7.z,q7.w};

            float p1  = __expf(-dtv);
            float p2  = p1*p1;
            float p4  = p2*p2;
            float p8  = p4*p4;
            float p16 = p8*p8;
            float du  = dtv * u;

            float y0 = 0.f, y1 = 0.f, y2 = 0.f, y3 = 0.f;
            #pragma unroll
            for (int s = 0; s < SSTATE; s++) {
                const int e = s + 1;
                float pw = 1.0f;
                if (e & 1)  pw *= p1;
                if (e & 2)  pw *= p2;
                if (e & 4)  pw *= p4;
                if (e & 8)  pw *= p8;
                if (e & 16) pw *= p16;
                float dA = pw * fmaf(eps[s], dtv, 1.0f);
                h[s] = fmaf(dA, h[s], du * Bv[s]);
                float t2 = h[s] * Cv[s];
                if      ((s & 3) == 0) y0 += t2;
                else if ((s & 3) == 1) y1 += t2;
                else if ((s & 3) == 2) y2 += t2;
                else                   y3 += t2;
            }
            float ys = (y0 + y1) + (y2 + y3);
            float o  = fmaf(u, Dv, ys) * silu_f(zv);
            unsigned short oh, ol;
            split1h(o, oh, ol);
            size_t oidx = (size_t)b * LL * DD + (size_t)l * DD + c;
            *(unsigned short*)(yh + oidx) = oh;
            *(unsigned short*)(yl + oidx) = ol;
        }
        __syncthreads();
    }
}

// ---------------- launch ---------------------------------------------------
extern "C" void kernel_launch(void* const* d_in, const int* in_sizes, int n_in,
                              void* d_out, int out_size)
{
    const float* x      = (const float*)d_in[0];
    const float* W_in   = (const float*)d_in[1];
    const float* conv_w = (const float*)d_in[2];
    const float* conv_b = (const float*)d_in[3];
    const float* W_x    = (const float*)d_in[4];
    const float* W_dt   = (const float*)d_in[5];
    const float* b_dt   = (const float*)d_in[6];
    const float* A_log  = (const float*)d_in[7];
    const float* D      = (const float*)d_in[8];
    const float* W_out  = (const float*)d_in[9];
    float* out = (float*)d_out;

    float *xz, *xc, *xdbl, *xpart, *dtb;
    __half *xh, *xl, *wih, *woh, *yh, *yl;
    __half *wdh, *wdl, *wxh, *wxl, *xch, *xcl, *dih, *dil;
    cudaGetSymbolAddress((void**)&xz,    g_xz);
    cudaGetSymbolAddress((void**)&xc,    g_xc);
    cudaGetSymbolAddress((void**)&xdbl,  g_xdbl);
    cudaGetSymbolAddress((void**)&xpart, g_xpart);
    cudaGetSymbolAddress((void**)&dtb,   g_dt);
    cudaGetSymbolAddress((void**)&xh,  g_xh);  cudaGetSymbolAddress((void**)&xl,  g_xl);
    cudaGetSymbolAddress((void**)&wih, g_wih);
    cudaGetSymbolAddress((void**)&woh, g_woh);
    cudaGetSymbolAddress((void**)&wdh, g_wdh); cudaGetSymbolAddress((void**)&wdl, g_wdl);
    cudaGetSymbolAddress((void**)&wxh, g_wxh); cudaGetSymbolAddress((void**)&wxl, g_wxl);
    cudaGetSymbolAddress((void**)&xch, g_xch); cudaGetSymbolAddress((void**)&xcl, g_xcl);
    cudaGetSymbolAddress((void**)&dih, g_dih); cudaGetSymbolAddress((void**)&dil, g_dil);
    cudaGetSymbolAddress((void**)&yh,  g_yh);  cudaGetSymbolAddress((void**)&yl,  g_yl);

    cudaFuncSetAttribute((const void*)mma_gemm128h<0,false>, cudaFuncAttributeMaxDynamicSharedMemorySize, H_SMEM2);
    cudaFuncSetAttribute((const void*)mma_gemm128h<0,true>,  cudaFuncAttributeMaxDynamicSharedMemorySize, H_SMEM3);
    cudaFuncSetAttribute((const void*)mma_gemm128h<1,true>,  cudaFuncAttributeMaxDynamicSharedMemorySize, H_SMEM3);
    cudaFuncSetAttribute((const void*)scan_kernel,           cudaFuncAttributeMaxDynamicSharedMemorySize, SCAN_SMEM);

    // idx0: split x -> fp16 hi/lo
    split_h_kernel<<<(TT*HH/4 + 255)/256, 256>>>(x, xh, xl, TT*HH/4);
    // idx1: W_in^T -> fp16 hi (fast 64x64)
    trsplit_h64<<<dim3(2*DD/64, HH/64), 256>>>(W_in, wih, HH, 2*DD);
    // idx2: W_out^T -> fp16 hi
    trsplit_h64<<<dim3(HH/64, DD/64), 256>>>(W_out, woh, DD, HH);
    // idx3: GEMM1 (ncu capture slot): xz = x @ W_in  (2048 x 8192, K=2048)
    mma_gemm128h<0,false><<<dim3(2*DD/128, TT/128), 256, H_SMEM2>>>(
        xh, xl, wih, nullptr, xz, TT, 2*DD, HH, HH, nullptr);
    // idx4: W_dt^T -> fp16 hi+lo
    trsplit_h2_64<<<dim3(DD/64, RR/64), 256>>>(W_dt, wdh, wdl, RR, DD);
    // idx5: W_x^T -> fp16 hi+lo (padded; 32-wide for C=160)
    trsplit_h2_32<<<dim3(XDBL_N/32, DD/32), 256>>>(W_x, wxh, wxl, DD, XDBL_N);
    // idx6: conv + silu -> xc + fp16 split
    conv_silu_kernel<<<(TT*(DD/4) + 255)/256, 256>>>(xz, conv_w, conv_b, xc, xch, xcl);
    // idx7: x_dbl split-K (fp16 3-pass)
    mma_gemm128h<0,true><<<dim3(XPAD/128, TT/128, NSPLITK), 256, H_SMEM3>>>(
        xch, xcl, wxh, wxl, xpart, TT, XPAD, DD, DD/NSPLITK, nullptr);
    // idx8: reduce + dt_in split
    xdbl_reduce_kernel<<<(TT*(XPAD/4) + 255)/256, 256>>>(xpart, xdbl, dih, dil);
    // idx9: dt GEMM + softplus (fp16 3-pass, K=128)
    mma_gemm128h<1,true><<<dim3(DD/128, TT/128), 256, H_SMEM3>>>(
        dih, dil, wdh, wdl, dtb, TT, DD, RR, RR, b_dt);
    // idx10: scan + fused mix -> yh/yl
    scan_kernel<<<dim3(DD/128, BBATCH), 128, SCAN_SMEM>>>(
        xc, dtb, xdbl, A_log, xz, D, yh, yl);
    // idx11: out = y @ W_out  (2048 x 2048, K=4096)
    mma_gemm128h<0,false><<<dim3(HH/128, TT/128), 256, H_SMEM2>>>(
        yh, yl, woh, nullptr, out, TT, HH, DD, DD, nullptr);
}

// round 15
// speedup vs baseline: 1.9830x; 1.0440x over previous
#include <cuda_runtime.h>
#include <cuda_fp16.h>
#include <math.h>
#include <stdint.h>

// Problem dims (fixed)
#define BBATCH 2
#define LL   1024
#define HH   2048
#define DD   4096      // d = H*E
#define SSTATE 16
#define RR   128
#define TT   2048      // B*L tokens
#define XDBL_N 160     // R + 2S
#define XPAD 256       // padded x_dbl width
#define NSPLITK 8

// ---------------- scratch (static device globals; no allocation) ----------
__device__ float g_xz  [(size_t)TT * 2 * DD];
__device__ float g_xc  [(size_t)TT * DD];
__device__ float g_xdbl[(size_t)TT * XPAD];                 // padded
__device__ float g_xpart[(size_t)NSPLITK * TT * XPAD];      // split-K partials
__device__ float g_dt  [(size_t)TT * DD];

// fp16 split operands
__device__ __half g_xh [(size_t)TT * HH];
__device__ __half g_xl [(size_t)TT * HH];
__device__ __half g_wih[(size_t)2 * DD * HH];   // W_in^T  [8192][2048] (hi only)
__device__ __half g_woh[(size_t)HH * DD];       // W_out^T [2048][4096] (hi only)
__device__ __half g_yh [(size_t)TT * DD];
__device__ __half g_yl [(size_t)TT * DD];
__device__ __half g_wdh[(size_t)DD * RR];       // W_dt^T  [4096][128] hi
__device__ __half g_wdl[(size_t)DD * RR];       //                     lo
__device__ __half g_wxh[(size_t)XPAD * DD];     // W_x^T [256pad][4096] hi (rows 160+ zero)
__device__ __half g_wxl[(size_t)XPAD * DD];
__device__ __half g_xch[(size_t)TT * DD];       // split of xc
__device__ __half g_xcl[(size_t)TT * DD];
__device__ __half g_dih[(size_t)TT * RR];       // dt_in [2048][128]
__device__ __half g_dil[(size_t)TT * RR];

// ---------------- small helpers ------------------------------------------
__device__ __forceinline__ float silu_f(float x) { return x / (1.0f + __expf(-x)); }
__device__ __forceinline__ float softplus_f(float x) {
    return fmaxf(x, 0.0f) + log1pf(__expf(-fabsf(x)));
}
__device__ __forceinline__ uint32_t smem_u32(const void* p) {
    uint32_t a;
    asm("{ .reg .u64 t; cvta.to.shared.u64 t, %1; cvt.u32.u64 %0, t; }" : "=r"(a) : "l"(p));
    return a;
}
__device__ __forceinline__ unsigned short h_bits(__half h) {
    unsigned short u; *(__half*)&u = h; return u;
}
__device__ __forceinline__ void split1h(float v, unsigned short& h, unsigned short& l) {
    __half hb = __float2half(v);
    __half lb = __float2half(v - __half2float(hb));
    h = h_bits(hb); l = h_bits(lb);
}
__device__ __forceinline__ void cp_async16(uint32_t dst, const void* src) {
    asm volatile("cp.async.cg.shared.global [%0], [%1], 16;" :: "r"(dst), "l"(src));
}
__device__ __forceinline__ void ldsm_x4(uint32_t addr, uint32_t& r0, uint32_t& r1,
                                        uint32_t& r2, uint32_t& r3) {
    asm volatile("ldmatrix.sync.aligned.m8n8.x4.shared.b16 {%0,%1,%2,%3}, [%4];"
                 : "=r"(r0), "=r"(r1), "=r"(r2), "=r"(r3) : "r"(addr));
}
__device__ __forceinline__ void mma_f16(float* c, const uint32_t* a,
                                        uint32_t b0, uint32_t b1) {
    asm volatile(
        "mma.sync.aligned.m16n8k16.row.col.f32.f16.f16.f32 "
        "{%0,%1,%2,%3}, {%4,%5,%6,%7}, {%8,%9}, {%0,%1,%2,%3};"
        : "+f"(c[0]), "+f"(c[1]), "+f"(c[2]), "+f"(c[3])
        : "r"(a[0]), "r"(a[1]), "r"(a[2]), "r"(a[3]), "r"(b0), "r"(b1));
}

// ======== fp16 GEMM: 128x128 tile, PASSES in {1,2,3} =======================
// PASSES=1: ah*bh.  PASSES=2: + al*bh.  PASSES=3: + ah*bl.
// BK=64, 2-stage cp.async, 256 threads, warp tile 32x64.
// EPI: 0 plain, 1 = +bias then softplus.
#define H_AT 16384

template<int EPI, int PASSES>
__global__ __launch_bounds__(256, PASSES >= 3 ? 1 : 2)
void mma_gemm128h(const __half* __restrict__ Ah, const __half* __restrict__ Al,
                  const __half* __restrict__ Bh, const __half* __restrict__ Bl,
                  float* __restrict__ C, int M, int N, int ldk, int kLen,
                  const float* __restrict__ bias)
{
    constexpr uint32_t STAGE = (PASSES + 1) * H_AT;   // tiles: Ah,Bh[,Al][,Bl]
    extern __shared__ char smem_raw[];
    const uint32_t sb = (smem_u32(smem_raw) + 1023u) & ~1023u;

    const int tid  = threadIdx.x;
    const int lane = tid & 31;
    const int wid  = tid >> 5;
    const int wm   = wid & 3;        // 4 m-slabs of 32
    const int wn   = wid >> 2;       // 2 n-slabs of 64
    const int bm = blockIdx.y * 128;
    const int bn = blockIdx.x * 128;
    const int kOff = blockIdx.z * kLen;
    C += (size_t)blockIdx.z * (size_t)M * (size_t)N;

    uint32_t sw[4]; uint32_t gofs[4];
    #pragma unroll
    for (int i = 0; i < 4; i++) {
        int c = i * 256 + tid;
        int row = c >> 3, kb = c & 7;
        uint32_t o = (uint32_t)(row * 128 + kb * 16);
        sw[i]   = o ^ ((o >> 3) & 0x70);
        gofs[i] = (uint32_t)(row * ldk * 2 + kb * 16);
    }
    const char* srcAh = (const char*)(Ah + (size_t)bm * ldk + kOff);
    const char* srcBh = (const char*)(Bh + (size_t)bn * ldk + kOff);
    const char* srcAl = (PASSES >= 2) ? (const char*)(Al + (size_t)bm * ldk + kOff) : nullptr;
    const char* srcBl = (PASSES >= 3) ? (const char*)(Bl + (size_t)bn * ldk + kOff) : nullptr;

    float acc[2][8][4];
    #pragma unroll
    for (int mi = 0; mi < 2; mi++)
        #pragma unroll
        for (int ni = 0; ni < 8; ni++)
            #pragma unroll
            for (int r = 0; r < 4; r++) acc[mi][ni][r] = 0.0f;

    const int NK = kLen >> 6;

    auto load_stage = [&](int kblk, int s) {
        uint32_t base = sb + (uint32_t)s * STAGE;
        uint32_t kadd = (uint32_t)kblk * 128;
        #pragma unroll
        for (int i = 0; i < 4; i++) cp_async16(base + sw[i],          srcAh + kadd + gofs[i]);
        #pragma unroll
        for (int i = 0; i < 4; i++) cp_async16(base + H_AT + sw[i],   srcBh + kadd + gofs[i]);
        if (PASSES >= 2) {
            #pragma unroll
            for (int i = 0; i < 4; i++) cp_async16(base + 2*H_AT + sw[i], srcAl + kadd + gofs[i]);
        }
        if (PASSES >= 3) {
            #pragma unroll
            for (int i = 0; i < 4; i++) cp_async16(base + 3*H_AT + sw[i], srcBl + kadd + gofs[i]);
        }
        asm volatile("cp.async.commit_group;" ::: "memory");
    };

    load_stage(0, 0);

    for (int kblk = 0; kblk < NK; kblk++) {
        int s = kblk & 1;
        if (kblk + 1 < NK) {
            load_stage(kblk + 1, 1 - s);
            asm volatile("cp.async.wait_group 1;" ::: "memory");
        } else {
            asm volatile("cp.async.wait_group 0;" ::: "memory");
        }
        __syncthreads();

        uint32_t base = sb + (uint32_t)s * STAGE;
        uint32_t tAh = base, tBh = base + H_AT;
        uint32_t tAl = base + 2*H_AT, tBl = base + 3*H_AT;

        #pragma unroll
        for (int kk = 0; kk < 4; kk++) {
            const int kb = kk * 32;
            uint32_t aoff[2], boff[4];
            #pragma unroll
            for (int mi = 0; mi < 2; mi++) {
                int mrow = wm * 32 + mi * 16 + (lane & 15);
                int ko   = kb + ((lane >> 4) << 4);
                uint32_t o = (uint32_t)(mrow * 128 + ko);
                aoff[mi] = o ^ ((o >> 3) & 0x70);
            }
            #pragma unroll
            for (int nj = 0; nj < 4; nj++) {
                int nrow = wn * 64 + nj * 16 + (lane & 7) + ((lane >> 4) << 3);
                int ko   = kb + (((lane >> 3) & 1) << 4);
                uint32_t o = (uint32_t)(nrow * 128 + ko);
                boff[nj] = o ^ ((o >> 3) & 0x70);
            }

            uint32_t ah[8], bb[16], tt[8];
            #pragma unroll
            for (int mi = 0; mi < 2; mi++)
                ldsm_x4(tAh + aoff[mi], ah[mi*4+0], ah[mi*4+1], ah[mi*4+2], ah[mi*4+3]);
            #pragma unroll
            for (int nj = 0; nj < 4; nj++)
                ldsm_x4(tBh + boff[nj], bb[nj*4+0], bb[nj*4+1], bb[nj*4+2], bb[nj*4+3]);
            // pass 0: ah * bh
            #pragma unroll
            for (int mi = 0; mi < 2; mi++)
                #pragma unroll
                for (int ni = 0; ni < 8; ni++)
                    mma_f16(acc[mi][ni], &ah[mi*4], bb[ni*2], bb[ni*2+1]);
            if (PASSES >= 2) {
                // pass 1: al * bh
                #pragma unroll
                for (int mi = 0; mi < 2; mi++)
                    ldsm_x4(tAl + aoff[mi], tt[mi*4+0], tt[mi*4+1], tt[mi*4+2], tt[mi*4+3]);
                #pragma unroll
                for (int mi = 0; mi < 2; mi++)
                    #pragma unroll
                    for (int ni = 0; ni < 8; ni++)
                        mma_f16(acc[mi][ni], &tt[mi*4], bb[ni*2], bb[ni*2+1]);
            }
            if (PASSES >= 3) {
                // pass 2: ah * bl (reuse bb)
                #pragma unroll
                for (int nj = 0; nj < 4; nj++)
                    ldsm_x4(tBl + boff[nj], bb[nj*4+0], bb[nj*4+1], bb[nj*4+2], bb[nj*4+3]);
                #pragma unroll
                for (int mi = 0; mi < 2; mi++)
                    #pragma unroll
                    for (int ni = 0; ni < 8; ni++)
                        mma_f16(acc[mi][ni], &ah[mi*4], bb[ni*2], bb[ni*2+1]);
            }
        }
        __syncthreads();
    }

    #pragma unroll
    for (int mi = 0; mi < 2; mi++) {
        #pragma unroll
        for (int ni = 0; ni < 8; ni++) {
            int row = bm + wm * 32 + mi * 16 + (lane >> 2);
            int col = bn + wn * 64 + ni * 8 + (lane & 3) * 2;
            float2 v0 = make_float2(acc[mi][ni][0], acc[mi][ni][1]);
            float2 v1 = make_float2(acc[mi][ni][2], acc[mi][ni][3]);
            if (EPI == 1) {
                float b0 = __ldg(bias + col), b1 = __ldg(bias + col + 1);
                v0.x = softplus_f(v0.x + b0); v0.y = softplus_f(v0.y + b1);
                v1.x = softplus_f(v1.x + b0); v1.y = softplus_f(v1.y + b1);
            }
            *(float2*)(C + (size_t)row * N + col)       = v0;
            *(float2*)(C + (size_t)(row + 8) * N + col) = v1;
        }
    }
}

#define H_SMEM1 (2 * 2 * H_AT + 1024)
#define H_SMEM2 (2 * 3 * H_AT + 1024)
#define H_SMEM3 (2 * 4 * H_AT + 1024)

// ---------------- prep kernels --------------------------------------------
__global__ __launch_bounds__(256)
void split_h_kernel(const float* __restrict__ in, __half* __restrict__ hi,
                    __half* __restrict__ lo, int n4)
{
    int i = blockIdx.x * 256 + threadIdx.x;
    if (i >= n4) return;
    float4 v = ((const float4*)in)[i];
    ushort4 h, l;
    split1h(v.x, h.x, l.x); split1h(v.y, h.y, l.y);
    split1h(v.z, h.z, l.z); split1h(v.w, h.w, l.w);
    ((ushort4*)hi)[i] = h;
    ((ushort4*)lo)[i] = l;
}

// fast 64x64 transpose, hi only: in [R][C] fp32 -> out [C][R] half
__global__ __launch_bounds__(256)
void trsplit_h64(const float* __restrict__ in, __half* __restrict__ oh, int R, int C)
{
    __shared__ float t[64][65];
    int c0 = blockIdx.x * 64, r0 = blockIdx.y * 64;
    int tid = threadIdx.x;
    #pragma unroll
    for (int k = 0; k < 4; k++) {
        int idx = k * 256 + tid;
        int row = idx >> 4, c4 = idx & 15;
        float4 v = *(const float4*)(in + (size_t)(r0 + row) * C + c0 + c4 * 4);
        t[row][c4*4+0] = v.x; t[row][c4*4+1] = v.y;
        t[row][c4*4+2] = v.z; t[row][c4*4+3] = v.w;
    }
    __syncthreads();
    #pragma unroll
    for (int k = 0; k < 4; k++) {
        int idx = k * 256 + tid;
        int cc = idx >> 4, rq = idx & 15;
        int rr = rq * 4;
        ushort4 h;
        h.x = h_bits(__float2half(t[rr+0][cc]));
        h.y = h_bits(__float2half(t[rr+1][cc]));
        h.z = h_bits(__float2half(t[rr+2][cc]));
        h.w = h_bits(__float2half(t[rr+3][cc]));
        *(ushort4*)(oh + (size_t)(c0 + cc) * R + r0 + rr) = h;
    }
}

// fast 64x64 transpose, hi+lo
__global__ __launch_bounds__(256)
void trsplit_h2_64(const float* __restrict__ in, __half* __restrict__ oh,
                   __half* __restrict__ ol, int R, int C)
{
    __shared__ float t[64][65];
    int c0 = blockIdx.x * 64, r0 = blockIdx.y * 64;
    int tid = threadIdx.x;
    #pragma unroll
    for (int k = 0; k < 4; k++) {
        int idx = k * 256 + tid;
        int row = idx >> 4, c4 = idx & 15;
        float4 v = *(const float4*)(in + (size_t)(r0 + row) * C + c0 + c4 * 4);
        t[row][c4*4+0] = v.x; t[row][c4*4+1] = v.y;
        t[row][c4*4+2] = v.z; t[row][c4*4+3] = v.w;
    }
    __syncthreads();
    #pragma unroll
    for (int k = 0; k < 4; k++) {
        int idx = k * 256 + tid;
        int cc = idx >> 4, rq = idx & 15;
        int rr = rq * 4;
        ushort4 h, l;
        split1h(t[rr+0][cc], h.x, l.x);
        split1h(t[rr+1][cc], h.y, l.y);
        split1h(t[rr+2][cc], h.z, l.z);
        split1h(t[rr+3][cc], h.w, l.w);
        size_t o = ((size_t)(c0 + cc) * R + r0 + rr);
        *(ushort4*)(oh + o) = h;
        *(ushort4*)(ol + o) = l;
    }
}

// 32-wide transpose hi+lo (for W_x: C=160)
__global__ __launch_bounds__(256)
void trsplit_h2_32(const float* __restrict__ in, __half* __restrict__ oh,
                   __half* __restrict__ ol, int R, int C)
{
    __shared__ float t[32][33];
    int c0 = blockIdx.x * 32, r0 = blockIdx.y * 32;
    int tx = threadIdx.x & 31, ty = threadIdx.x >> 5;
    #pragma unroll
    for (int j = 0; j < 4; j++)
        t[ty + 8 * j][tx] = in[(size_t)(r0 + ty + 8 * j) * C + c0 + tx];
    __syncthreads();
    #pragma unroll
    for (int j = 0; j < 4; j++) {
        float v = t[tx][ty + 8 * j];
        unsigned short h, l; split1h(v, h, l);
        size_t o = (size_t)(c0 + ty + 8 * j) * R + r0 + tx;
        *(unsigned short*)(oh + o) = h;
        *(unsigned short*)(ol + o) = l;
    }
}

// reduce split-K partials -> xdbl (padded) + fused dt_in fp16 split
__global__ __launch_bounds__(256)
void xdbl_reduce_kernel(const float* __restrict__ part, float* __restrict__ xdbl,
                        __half* __restrict__ dih, __half* __restrict__ dil)
{
    int i = blockIdx.x * 256 + threadIdx.x;
    if (i >= TT * (XPAD / 4)) return;
    float4 s = make_float4(0.f, 0.f, 0.f, 0.f);
    #pragma unroll
    for (int z = 0; z < NSPLITK; z++) {
        float4 v = ((const float4*)(part + (size_t)z * TT * XPAD))[i];
        s.x += v.x; s.y += v.y; s.z += v.z; s.w += v.w;
    }
    ((float4*)xdbl)[i] = s;
    int col = (i & (XPAD/4 - 1)) * 4;
    if (col < RR) {
        int row = i / (XPAD/4);
        ushort4 h, l;
        split1h(s.x, h.x, l.x); split1h(s.y, h.y, l.y);
        split1h(s.z, h.z, l.z); split1h(s.w, h.w, l.w);
        size_t o = ((size_t)row * RR + col) >> 2;
        ((ushort4*)dih)[o] = h;
        ((ushort4*)dil)[o] = l;
    }
}

// ---------------- depthwise conv3 + bias + SiLU (+ fp16 split out) --------
__global__ __launch_bounds__(256)
void conv_silu_kernel(const float* __restrict__ xz, const float* __restrict__ w,
                      const float* __restrict__ bias, float* __restrict__ xc,
                      __half* __restrict__ xch, __half* __restrict__ xcl)
{
    int i = blockIdx.x * blockDim.x + threadIdx.x;
    const int NW = TT * (DD/4);
    if (i >= NW) return;
    int c4 = i % (DD/4);
    int t  = i / (DD/4);
    int l  = t & (LL - 1);
    int c  = c4 * 4;

    const float* p = xz + (size_t)t * (2*DD) + c;
    float4 x0 = *(const float4*)p;
    float4 xm = (l > 0)      ? *(const float4*)(p - 2*DD) : make_float4(0,0,0,0);
    float4 xp = (l < LL - 1) ? *(const float4*)(p + 2*DD) : make_float4(0,0,0,0);

    float xmv[4] = {xm.x, xm.y, xm.z, xm.w};
    float x0v[4] = {x0.x, x0.y, x0.z, x0.w};
    float xpv[4] = {xp.x, xp.y, xp.z, xp.w};
    float out[4];
    #pragma unroll
    for (int j = 0; j < 4; j++) {
        int cc = c + j;
        float v = xmv[j]*w[cc*3+0] + x0v[j]*w[cc*3+1] + xpv[j]*w[cc*3+2] + bias[cc];
        out[j] = silu_f(v);
    }
    *(float4*)(xc + (size_t)t*DD + c) = make_float4(out[0], out[1], out[2], out[3]);
    ushort4 h, l4;
    split1h(out[0], h.x, l4.x); split1h(out[1], h.y, l4.y);
    split1h(out[2], h.z, l4.z); split1h(out[3], h.w, l4.w);
    size_t o = ((size_t)t*DD + c) >> 2;
    ((ushort4*)xch)[o] = h;
    ((ushort4*)xcl)[o] = l4;
}

// ---------------- selective scan + fused gated mix ------------------------
#define SCH 32
#define SNC (LL / SCH)
#define SCAN_SMEM ((24576 + 2048) * 4)

__global__ __launch_bounds__(128)
void scan_kernel(const float* __restrict__ xc, const float* __restrict__ dt,
                 const float* __restrict__ xdbl, const float* __restrict__ A_log,
                 const float* __restrict__ xz, const float* __restrict__ Dp,
                 __half* __restrict__ yh, __half* __restrict__ yl)
{
    extern __shared__ float sm[];
    float* sU  = sm;
    float* sDT = sm + 8192;
    float* sZ  = sm + 16384;
    float* sBC = sm + 24576;

    const int tid = threadIdx.x;
    const int c0  = blockIdx.x * 128;
    const int c   = c0 + tid;
    const int b   = blockIdx.y;

    float eps[SSTATE];
    #pragma unroll
    for (int s = 0; s < SSTATE; s++)
        eps[s] = (float)(s + 1) - expf(A_log[(size_t)c*SSTATE + s]);
    const float Dv = Dp[c];

    float h[SSTATE];
    #pragma unroll
    for (int s = 0; s < SSTATE; s++) h[s] = 0.0f;

    const float* xcrow = xc   + (size_t)b * LL * DD + c0;
    const float* dtrow = dt   + (size_t)b * LL * DD + c0;
    const float* zrow  = xz   + (size_t)b * LL * (2*DD) + DD + c0;
    const float* bcrow = xdbl + (size_t)b * LL * XPAD + RR;

    const uint32_t sb = smem_u32(sm);
    auto load_chunk = [&](int lc, int buf) {
        const int l0 = lc * SCH;
        #pragma unroll
        for (int k = 0; k < 8; k++) {
            int idx = k * 128 + tid;
            int r = idx >> 5, q = idx & 31;
            uint32_t so = (uint32_t)(((buf * SCH + r) * 128 + q * 4) * 4);
            cp_async16(sb + so,           xcrow + (size_t)(l0 + r) * DD     + q * 4);
            cp_async16(sb + 32768 + so,   dtrow + (size_t)(l0 + r) * DD     + q * 4);
            cp_async16(sb + 65536 + so,   zrow  + (size_t)(l0 + r) * (2*DD) + q * 4);
        }
        #pragma unroll
        for (int k = 0; k < 2; k++) {
            int idx = k * 128 + tid;
            int r = idx >> 3, q = idx & 7;
            uint32_t so = (uint32_t)(98304 + ((buf * SCH + r) * 32 + q * 4) * 4);
            cp_async16(sb + so, bcrow + (size_t)(l0 + r) * XPAD + q * 4);
        }
        asm volatile("cp.async.commit_group;" ::: "memory");
    };

    load_chunk(0, 0);

    for (int lc = 0; lc < SNC; lc++) {
        const int buf = lc & 1;
        if (lc + 1 < SNC) {
            load_chunk(lc + 1, 1 - buf);
            asm volatile("cp.async.wait_group 1;" ::: "memory");
        } else {
            asm volatile("cp.async.wait_group 0;" ::: "memory");
        }
        __syncthreads();

        #pragma unroll 4
        for (int ll = 0; ll < SCH; ll++) {
            const int l = lc * SCH + ll;
            const int ro = (buf * SCH + ll);
            float u   = sU [ro * 128 + tid];
            float dtv = sDT[ro * 128 + tid];
            float zv  = sZ [ro * 128 + tid];
            const float4* bc = (const float4*)&sBC[ro * 32];
            float4 q0 = bc[0], q1 = bc[1], q2 = bc[2], q3 = bc[3];
            float4 q4 = bc[4], q5 = bc[5], q6 = bc[6], q7 = bc[7];
            float Bv[SSTATE] = {q0.x,q0.y,q0.z,q0.w, q1.x,q1.y,q1.z,q1.w,
                                q2.x,q2.y,q2.z,q2.w, q3.x,q3.y,q3.z,q3.w};
            float Cv[SSTATE] = {q4.x,q4.y,q4.z,q4.w, q5.x,q5.y,q5.z,q5.w,
                                q6.x,q6.y,q6.z,q6.w, q7.x,q7.y,q7.z,q7.w};

            float p1  = __expf(-dtv);
            float p2  = p1*p1;
            float p4  = p2*p2;
            float p8  = p4*p4;
            float p16 = p8*p8;
            float du  = dtv * u;

            float y0 = 0.f, y1 = 0.f, y2 = 0.f, y3 = 0.f;
            #pragma unroll
            for (int s = 0; s < SSTATE; s++) {
                const int e = s + 1;
                float pw = 1.0f;
                if (e & 1)  pw *= p1;
                if (e & 2)  pw *= p2;
                if (e & 4)  pw *= p4;
                if (e & 8)  pw *= p8;
                if (e & 16) pw *= p16;
                float dA = pw * fmaf(eps[s], dtv, 1.0f);
                h[s] = fmaf(dA, h[s], du * Bv[s]);
                float t2 = h[s] * Cv[s];
                if      ((s & 3) == 0) y0 += t2;
                else if ((s & 3) == 1) y1 += t2;
                else if ((s & 3) == 2) y2 += t2;
                else                   y3 += t2;
            }
            float ys = (y0 + y1) + (y2 + y3);
            float o  = fmaf(u, Dv, ys) * silu_f(zv);
            unsigned short oh, ol;
            split1h(o, oh, ol);
            size_t oidx = (size_t)b * LL * DD + (size_t)l * DD + c;
            *(unsigned short*)(yh + oidx) = oh;
            *(unsigned short*)(yl + oidx) = ol;
        }
        __syncthreads();
    }
}

// ---------------- launch ---------------------------------------------------
extern "C" void kernel_launch(void* const* d_in, const int* in_sizes, int n_in,
                              void* d_out, int out_size)
{
    const float* x      = (const float*)d_in[0];
    const float* W_in   = (const float*)d_in[1];
    const float* conv_w = (const float*)d_in[2];
    const float* conv_b = (const float*)d_in[3];
    const float* W_x    = (const float*)d_in[4];
    const float* W_dt   = (const float*)d_in[5];
    const float* b_dt   = (const float*)d_in[6];
    const float* A_log  = (const float*)d_in[7];
    const float* D      = (const float*)d_in[8];
    const float* W_out  = (const float*)d_in[9];
    float* out = (float*)d_out;

    float *xz, *xc, *xdbl, *xpart, *dtb;
    __half *xh, *xl, *wih, *woh, *yh, *yl;
    __half *wdh, *wdl, *wxh, *wxl, *xch, *xcl, *dih, *dil;
    cudaGetSymbolAddress((void**)&xz,    g_xz);
    cudaGetSymbolAddress((void**)&xc,    g_xc);
    cudaGetSymbolAddress((void**)&xdbl,  g_xdbl);
    cudaGetSymbolAddress((void**)&xpart, g_xpart);
    cudaGetSymbolAddress((void**)&dtb,   g_dt);
    cudaGetSymbolAddress((void**)&xh,  g_xh);  cudaGetSymbolAddress((void**)&xl,  g_xl);
    cudaGetSymbolAddress((void**)&wih, g_wih);
    cudaGetSymbolAddress((void**)&woh, g_woh);
    cudaGetSymbolAddress((void**)&wdh, g_wdh); cudaGetSymbolAddress((void**)&wdl, g_wdl);
    cudaGetSymbolAddress((void**)&wxh, g_wxh); cudaGetSymbolAddress((void**)&wxl, g_wxl);
    cudaGetSymbolAddress((void**)&xch, g_xch); cudaGetSymbolAddress((void**)&xcl, g_xcl);
    cudaGetSymbolAddress((void**)&dih, g_dih); cudaGetSymbolAddress((void**)&dil, g_dil);
    cudaGetSymbolAddress((void**)&yh,  g_yh);  cudaGetSymbolAddress((void**)&yl,  g_yl);

    cudaFuncSetAttribute((const void*)mma_gemm128h<0,1>, cudaFuncAttributeMaxDynamicSharedMemorySize, H_SMEM1);
    cudaFuncSetAttribute((const void*)mma_gemm128h<0,2>, cudaFuncAttributeMaxDynamicSharedMemorySize, H_SMEM2);
    cudaFuncSetAttribute((const void*)mma_gemm128h<0,3>, cudaFuncAttributeMaxDynamicSharedMemorySize, H_SMEM3);
    cudaFuncSetAttribute((const void*)mma_gemm128h<1,3>, cudaFuncAttributeMaxDynamicSharedMemorySize, H_SMEM3);
    cudaFuncSetAttribute((const void*)scan_kernel,       cudaFuncAttributeMaxDynamicSharedMemorySize, SCAN_SMEM);

    // idx0: split x -> fp16 hi/lo
    split_h_kernel<<<(TT*HH/4 + 255)/256, 256>>>(x, xh, xl, TT*HH/4);
    // idx1: W_in^T -> fp16 hi (fast 64x64)
    trsplit_h64<<<dim3(2*DD/64, HH/64), 256>>>(W_in, wih, HH, 2*DD);
    // idx2: W_out^T -> fp16 hi
    trsplit_h64<<<dim3(HH/64, DD/64), 256>>>(W_out, woh, DD, HH);
    // idx3 (ncu capture slot): xp half of GEMM1, 2-pass: xz[:, :4096]
    mma_gemm128h<0,2><<<dim3(DD/128, TT/128), 256, H_SMEM2>>>(
        xh, xl, wih, nullptr, xz, TT, 2*DD, HH, HH, nullptr);
    // idx4: z half of GEMM1, 1-pass: xz[:, 4096:]
    mma_gemm128h<0,1><<<dim3(DD/128, TT/128), 256, H_SMEM1>>>(
        xh, nullptr, wih + (size_t)DD * HH, nullptr, xz + DD, TT, 2*DD, HH, HH, nullptr);
    // idx5: W_dt^T -> fp16 hi+lo
    trsplit_h2_64<<<dim3(DD/64, RR/64), 256>>>(W_dt, wdh, wdl, RR, DD);
    // idx6: W_x^T -> fp16 hi+lo (padded; 32-wide for C=160)
    trsplit_h2_32<<<dim3(XDBL_N/32, DD/32), 256>>>(W_x, wxh, wxl, DD, XDBL_N);
    // idx7: conv + silu -> xc + fp16 split
    conv_silu_kernel<<<(TT*(DD/4) + 255)/256, 256>>>(xz, conv_w, conv_b, xc, xch, xcl);
    // idx8: x_dbl split-K (fp16 3-pass)
    mma_gemm128h<0,3><<<dim3(XPAD/128, TT/128, NSPLITK), 256, H_SMEM3>>>(
        xch, xcl, wxh, wxl, xpart, TT, XPAD, DD, DD/NSPLITK, nullptr);
    // idx9: reduce + dt_in split
    xdbl_reduce_kernel<<<(TT*(XPAD/4) + 255)/256, 256>>>(xpart, xdbl, dih, dil);
    // idx10: dt GEMM + softplus (fp16 3-pass, K=128)
    mma_gemm128h<1,3><<<dim3(DD/128, TT/128), 256, H_SMEM3>>>(
        dih, dil, wdh, wdl, dtb, TT, DD, RR, RR, b_dt);
    // idx11: scan + fused mix -> yh/yl
    scan_kernel<<<dim3(DD/128, BBATCH), 128, SCAN_SMEM>>>(
        xc, dtb, xdbl, A_log, xz, D, yh, yl);
    // idx12: out = y @ W_out  (2048 x 2048, K=4096), 2-pass
    mma_gemm128h<0,2><<<dim3(HH/128, TT/128), 256, H_SMEM2>>>(
        yh, yl, woh, nullptr, out, TT, HH, DD, DD, nullptr);
}

// round 16
// speedup vs baseline: 2.3549x; 1.1876x over previous
#include <cuda_runtime.h>
#include <cuda_fp16.h>
#include <math.h>
#include <stdint.h>

// Problem dims (fixed)
#define BBATCH 2
#define LL   1024
#define HH   2048
#define DD   4096      // d = H*E
#define SSTATE 16
#define RR   128
#define TT   2048      // B*L tokens
#define XDBL_N 160     // R + 2S
#define XPAD 256       // padded x_dbl width
#define NSPLITK 8

// ---------------- scratch (static device globals; no allocation) ----------
__device__ float g_xz  [(size_t)TT * 2 * DD];
__device__ float g_xc  [(size_t)TT * DD];
__device__ float g_xdbl[(size_t)TT * XPAD];                 // padded
__device__ float g_xpart[(size_t)NSPLITK * TT * XPAD];      // split-K partials
__device__ float g_dt  [(size_t)TT * DD];

// fp16 split operands
__device__ __half g_xh [(size_t)TT * HH];
__device__ __half g_xl [(size_t)TT * HH];
__device__ __half g_wih[(size_t)2 * DD * HH];   // W_in^T  [8192][2048] (hi only)
__device__ __half g_woh[(size_t)HH * DD];       // W_out^T [2048][4096] (hi only)
__device__ __half g_yh [(size_t)TT * DD];
__device__ __half g_yl [(size_t)TT * DD];
__device__ __half g_wdh[(size_t)DD * RR];       // W_dt^T  [4096][128] hi
__device__ __half g_wdl[(size_t)DD * RR];       //                     lo
__device__ __half g_wxh[(size_t)XPAD * DD];     // W_x^T [256pad][4096] hi (rows 160+ zero)
__device__ __half g_wxl[(size_t)XPAD * DD];
__device__ __half g_xch[(size_t)TT * DD];       // split of xc
__device__ __half g_xcl[(size_t)TT * DD];
__device__ __half g_dih[(size_t)TT * RR];       // dt_in [2048][128]
__device__ __half g_dil[(size_t)TT * RR];

// ---------------- small helpers ------------------------------------------
__device__ __forceinline__ float silu_f(float x) { return x / (1.0f + __expf(-x)); }
__device__ __forceinline__ float softplus_f(float x) {
    return fmaxf(x, 0.0f) + log1pf(__expf(-fabsf(x)));
}
__device__ __forceinline__ uint32_t smem_u32(const void* p) {
    uint32_t a;
    asm("{ .reg .u64 t; cvta.to.shared.u64 t, %1; cvt.u32.u64 %0, t; }" : "=r"(a) : "l"(p));
    return a;
}
__device__ __forceinline__ unsigned short h_bits(__half h) {
    unsigned short u; *(__half*)&u = h; return u;
}
__device__ __forceinline__ void split1h(float v, unsigned short& h, unsigned short& l) {
    __half hb = __float2half(v);
    __half lb = __float2half(v - __half2float(hb));
    h = h_bits(hb); l = h_bits(lb);
}
__device__ __forceinline__ void cp_async16(uint32_t dst, const void* src) {
    asm volatile("cp.async.cg.shared.global [%0], [%1], 16;" :: "r"(dst), "l"(src));
}
__device__ __forceinline__ void ldsm_x4(uint32_t addr, uint32_t& r0, uint32_t& r1,
                                        uint32_t& r2, uint32_t& r3) {
    asm volatile("ldmatrix.sync.aligned.m8n8.x4.shared.b16 {%0,%1,%2,%3}, [%4];"
                 : "=r"(r0), "=r"(r1), "=r"(r2), "=r"(r3) : "r"(addr));
}
__device__ __forceinline__ void mma_f16(float* c, const uint32_t* a,
                                        uint32_t b0, uint32_t b1) {
    asm volatile(
        "mma.sync.aligned.m16n8k16.row.col.f32.f16.f16.f32 "
        "{%0,%1,%2,%3}, {%4,%5,%6,%7}, {%8,%9}, {%0,%1,%2,%3};"
        : "+f"(c[0]), "+f"(c[1]), "+f"(c[2]), "+f"(c[3])
        : "r"(a[0]), "r"(a[1]), "r"(a[2]), "r"(a[3]), "r"(b0), "r"(b1));
}

// ======== fp16 GEMM: 128x128 tile, PASSES in {1,2,3} =======================
// PASSES=1: ah*bh.  PASSES=2: + al*bh (only for bn < n1pass).  PASSES=3: + ah*bl.
// BK=64, 2-stage cp.async, 256 threads, warp tile 32x64.
// EPI: 0 plain, 1 = +bias then softplus.
#define H_AT 16384

template<int EPI, int PASSES>
__global__ __launch_bounds__(256, PASSES >= 3 ? 1 : 2)
void mma_gemm128h(const __half* __restrict__ Ah, const __half* __restrict__ Al,
                  const __half* __restrict__ Bh, const __half* __restrict__ Bl,
                  float* __restrict__ C, int M, int N, int ldk, int kLen,
                  const float* __restrict__ bias, int n1pass)
{
    constexpr uint32_t STAGE = (PASSES + 1) * H_AT;   // tiles: Ah,Bh[,Al][,Bl]
    extern __shared__ char smem_raw[];
    const uint32_t sb = (smem_u32(smem_raw) + 1023u) & ~1023u;

    const int tid  = threadIdx.x;
    const int lane = tid & 31;
    const int wid  = tid >> 5;
    const int wm   = wid & 3;        // 4 m-slabs of 32
    const int wn   = wid >> 2;       // 2 n-slabs of 64
    const int bm = blockIdx.y * 128;
    const int bn = blockIdx.x * 128;
    const int kOff = blockIdx.z * kLen;
    C += (size_t)blockIdx.z * (size_t)M * (size_t)N;

    const bool doAl = (PASSES >= 2) && (bn < n1pass);

    uint32_t sw[4]; uint32_t gofs[4];
    #pragma unroll
    for (int i = 0; i < 4; i++) {
        int c = i * 256 + tid;
        int row = c >> 3, kb = c & 7;
        uint32_t o = (uint32_t)(row * 128 + kb * 16);
        sw[i]   = o ^ ((o >> 3) & 0x70);
        gofs[i] = (uint32_t)(row * ldk * 2 + kb * 16);
    }
    const char* srcAh = (const char*)(Ah + (size_t)bm * ldk + kOff);
    const char* srcBh = (const char*)(Bh + (size_t)bn * ldk + kOff);
    const char* srcAl = (PASSES >= 2) ? (const char*)(Al + (size_t)bm * ldk + kOff) : nullptr;
    const char* srcBl = (PASSES >= 3) ? (const char*)(Bl + (size_t)bn * ldk + kOff) : nullptr;

    float acc[2][8][4];
    #pragma unroll
    for (int mi = 0; mi < 2; mi++)
        #pragma unroll
        for (int ni = 0; ni < 8; ni++)
            #pragma unroll
            for (int r = 0; r < 4; r++) acc[mi][ni][r] = 0.0f;

    const int NK = kLen >> 6;

    auto load_stage = [&](int kblk, int s) {
        uint32_t base = sb + (uint32_t)s * STAGE;
        uint32_t kadd = (uint32_t)kblk * 128;
        #pragma unroll
        for (int i = 0; i < 4; i++) cp_async16(base + sw[i],          srcAh + kadd + gofs[i]);
        #pragma unroll
        for (int i = 0; i < 4; i++) cp_async16(base + H_AT + sw[i],   srcBh + kadd + gofs[i]);
        if (PASSES >= 2 && doAl) {
            #pragma unroll
            for (int i = 0; i < 4; i++) cp_async16(base + 2*H_AT + sw[i], srcAl + kadd + gofs[i]);
        }
        if (PASSES >= 3) {
            #pragma unroll
            for (int i = 0; i < 4; i++) cp_async16(base + 3*H_AT + sw[i], srcBl + kadd + gofs[i]);
        }
        asm volatile("cp.async.commit_group;" ::: "memory");
    };

    load_stage(0, 0);

    for (int kblk = 0; kblk < NK; kblk++) {
        int s = kblk & 1;
        if (kblk + 1 < NK) {
            load_stage(kblk + 1, 1 - s);
            asm volatile("cp.async.wait_group 1;" ::: "memory");
        } else {
            asm volatile("cp.async.wait_group 0;" ::: "memory");
        }
        __syncthreads();

        uint32_t base = sb + (uint32_t)s * STAGE;
        uint32_t tAh = base, tBh = base + H_AT;
        uint32_t tAl = base + 2*H_AT, tBl = base + 3*H_AT;

        #pragma unroll
        for (int kk = 0; kk < 4; kk++) {
            const int kb = kk * 32;
            uint32_t aoff[2], boff[4];
            #pragma unroll
            for (int mi = 0; mi < 2; mi++) {
                int mrow = wm * 32 + mi * 16 + (lane & 15);
                int ko   = kb + ((lane >> 4) << 4);
                uint32_t o = (uint32_t)(mrow * 128 + ko);
                aoff[mi] = o ^ ((o >> 3) & 0x70);
            }
            #pragma unroll
            for (int nj = 0; nj < 4; nj++) {
                int nrow = wn * 64 + nj * 16 + (lane & 7) + ((lane >> 4) << 3);
                int ko   = kb + (((lane >> 3) & 1) << 4);
                uint32_t o = (uint32_t)(nrow * 128 + ko);
                boff[nj] = o ^ ((o >> 3) & 0x70);
            }

            uint32_t ah[8], bb[16], tt[8];
            #pragma unroll
            for (int mi = 0; mi < 2; mi++)
                ldsm_x4(tAh + aoff[mi], ah[mi*4+0], ah[mi*4+1], ah[mi*4+2], ah[mi*4+3]);
            #pragma unroll
            for (int nj = 0; nj < 4; nj++)
                ldsm_x4(tBh + boff[nj], bb[nj*4+0], bb[nj*4+1], bb[nj*4+2], bb[nj*4+3]);
            // pass 0: ah * bh
            #pragma unroll
            for (int mi = 0; mi < 2; mi++)
                #pragma unroll
                for (int ni = 0; ni < 8; ni++)
                    mma_f16(acc[mi][ni], &ah[mi*4], bb[ni*2], bb[ni*2+1]);
            if (PASSES >= 2 && doAl) {
                // pass 1: al * bh
                #pragma unroll
                for (int mi = 0; mi < 2; mi++)
                    ldsm_x4(tAl + aoff[mi], tt[mi*4+0], tt[mi*4+1], tt[mi*4+2], tt[mi*4+3]);
                #pragma unroll
                for (int mi = 0; mi < 2; mi++)
                    #pragma unroll
                    for (int ni = 0; ni < 8; ni++)
                        mma_f16(acc[mi][ni], &tt[mi*4], bb[ni*2], bb[ni*2+1]);
            }
            if (PASSES >= 3) {
                // pass 2: ah * bl (reuse bb)
                #pragma unroll
                for (int nj = 0; nj < 4; nj++)
                    ldsm_x4(tBl + boff[nj], bb[nj*4+0], bb[nj*4+1], bb[nj*4+2], bb[nj*4+3]);
                #pragma unroll
                for (int mi = 0; mi < 2; mi++)
                    #pragma unroll
                    for (int ni = 0; ni < 8; ni++)
                        mma_f16(acc[mi][ni], &ah[mi*4], bb[ni*2], bb[ni*2+1]);
            }
        }
        __syncthreads();
    }

    #pragma unroll
    for (int mi = 0; mi < 2; mi++) {
        #pragma unroll
        for (int ni = 0; ni < 8; ni++) {
            int row = bm + wm * 32 + mi * 16 + (lane >> 2);
            int col = bn + wn * 64 + ni * 8 + (lane & 3) * 2;
            float2 v0 = make_float2(acc[mi][ni][0], acc[mi][ni][1]);
            float2 v1 = make_float2(acc[mi][ni][2], acc[mi][ni][3]);
            if (EPI == 1) {
                float b0 = __ldg(bias + col), b1 = __ldg(bias + col + 1);
                v0.x = softplus_f(v0.x + b0); v0.y = softplus_f(v0.y + b1);
                v1.x = softplus_f(v1.x + b0); v1.y = softplus_f(v1.y + b1);
            }
            *(float2*)(C + (size_t)row * N + col)       = v0;
            *(float2*)(C + (size_t)(row + 8) * N + col) = v1;
        }
    }
}

#define H_SMEM1 (2 * 2 * H_AT + 1024)
#define H_SMEM2 (2 * 3 * H_AT + 1024)
#define H_SMEM3 (2 * 4 * H_AT + 1024)

// ---------------- prep kernels --------------------------------------------
__global__ __launch_bounds__(256)
void split_h_kernel(const float* __restrict__ in, __half* __restrict__ hi,
                    __half* __restrict__ lo, int n4)
{
    int i = blockIdx.x * 256 + threadIdx.x;
    if (i >= n4) return;
    float4 v = ((const float4*)in)[i];
    ushort4 h, l;
    split1h(v.x, h.x, l.x); split1h(v.y, h.y, l.y);
    split1h(v.z, h.z, l.z); split1h(v.w, h.w, l.w);
    ((ushort4*)hi)[i] = h;
    ((ushort4*)lo)[i] = l;
}

// fast 64x64 transpose, hi only: in [R][C] fp32 -> out [C][R] half
__global__ __launch_bounds__(256)
void trsplit_h64(const float* __restrict__ in, __half* __restrict__ oh, int R, int C)
{
    __shared__ float t[64][65];
    int c0 = blockIdx.x * 64, r0 = blockIdx.y * 64;
    int tid = threadIdx.x;
    #pragma unroll
    for (int k = 0; k < 4; k++) {
        int idx = k * 256 + tid;
        int row = idx >> 4, c4 = idx & 15;
        float4 v = *(const float4*)(in + (size_t)(r0 + row) * C + c0 + c4 * 4);
        t[row][c4*4+0] = v.x; t[row][c4*4+1] = v.y;
        t[row][c4*4+2] = v.z; t[row][c4*4+3] = v.w;
    }
    __syncthreads();
    #pragma unroll
    for (int k = 0; k < 4; k++) {
        int idx = k * 256 + tid;
        int cc = idx >> 4, rq = idx & 15;
        int rr = rq * 4;
        ushort4 h;
        h.x = h_bits(__float2half(t[rr+0][cc]));
        h.y = h_bits(__float2half(t[rr+1][cc]));
        h.z = h_bits(__float2half(t[rr+2][cc]));
        h.w = h_bits(__float2half(t[rr+3][cc]));
        *(ushort4*)(oh + (size_t)(c0 + cc) * R + r0 + rr) = h;
    }
}

// fast 64x64 transpose, hi+lo
__global__ __launch_bounds__(256)
void trsplit_h2_64(const float* __restrict__ in, __half* __restrict__ oh,
                   __half* __restrict__ ol, int R, int C)
{
    __shared__ float t[64][65];
    int c0 = blockIdx.x * 64, r0 = blockIdx.y * 64;
    int tid = threadIdx.x;
    #pragma unroll
    for (int k = 0; k < 4; k++) {
        int idx = k * 256 + tid;
        int row = idx >> 4, c4 = idx & 15;
        float4 v = *(const float4*)(in + (size_t)(r0 + row) * C + c0 + c4 * 4);
        t[row][c4*4+0] = v.x; t[row][c4*4+1] = v.y;
        t[row][c4*4+2] = v.z; t[row][c4*4+3] = v.w;
    }
    __syncthreads();
    #pragma unroll
    for (int k = 0; k < 4; k++) {
        int idx = k * 256 + tid;
        int cc = idx >> 4, rq = idx & 15;
        int rr = rq * 4;
        ushort4 h, l;
        split1h(t[rr+0][cc], h.x, l.x);
        split1h(t[rr+1][cc], h.y, l.y);
        split1h(t[rr+2][cc], h.z, l.z);
        split1h(t[rr+3][cc], h.w, l.w);
        size_t o = ((size_t)(c0 + cc) * R + r0 + rr);
        *(ushort4*)(oh + o) = h;
        *(ushort4*)(ol + o) = l;
    }
}

// 32-wide transpose hi+lo (for W_x: C=160)
__global__ __launch_bounds__(256)
void trsplit_h2_32(const float* __restrict__ in, __half* __restrict__ oh,
                   __half* __restrict__ ol, int R, int C)
{
    __shared__ float t[32][33];
    int c0 = blockIdx.x * 32, r0 = blockIdx.y * 32;
    int tx = threadIdx.x & 31, ty = threadIdx.x >> 5;
    #pragma unroll
    for (int j = 0; j < 4; j++)
        t[ty + 8 * j][tx] = in[(size_t)(r0 + ty + 8 * j) * C + c0 + tx];
    __syncthreads();
    #pragma unroll
    for (int j = 0; j < 4; j++) {
        float v = t[tx][ty + 8 * j];
        unsigned short h, l; split1h(v, h, l);
        size_t o = (size_t)(c0 + ty + 8 * j) * R + r0 + tx;
        *(unsigned short*)(oh + o) = h;
        *(unsigned short*)(ol + o) = l;
    }
}

// reduce split-K partials -> xdbl (padded) + fused dt_in fp16 split
__global__ __launch_bounds__(256)
void xdbl_reduce_kernel(const float* __restrict__ part, float* __restrict__ xdbl,
                        __half* __restrict__ dih, __half* __restrict__ dil)
{
    int i = blockIdx.x * 256 + threadIdx.x;
    if (i >= TT * (XPAD / 4)) return;
    float4 s = make_float4(0.f, 0.f, 0.f, 0.f);
    #pragma unroll
    for (int z = 0; z < NSPLITK; z++) {
        float4 v = ((const float4*)(part + (size_t)z * TT * XPAD))[i];
        s.x += v.x; s.y += v.y; s.z += v.z; s.w += v.w;
    }
    ((float4*)xdbl)[i] = s;
    int col = (i & (XPAD/4 - 1)) * 4;
    if (col < RR) {
        int row = i / (XPAD/4);
        ushort4 h, l;
        split1h(s.x, h.x, l.x); split1h(s.y, h.y, l.y);
        split1h(s.z, h.z, l.z); split1h(s.w, h.w, l.w);
        size_t o = ((size_t)row * RR + col) >> 2;
        ((ushort4*)dih)[o] = h;
        ((ushort4*)dil)[o] = l;
    }
}

// ---------------- depthwise conv3 + bias + SiLU (+ fp16 split out) --------
__global__ __launch_bounds__(256)
void conv_silu_kernel(const float* __restrict__ xz, const float* __restrict__ w,
                      const float* __restrict__ bias, float* __restrict__ xc,
                      __half* __restrict__ xch, __half* __restrict__ xcl)
{
    int i = blockIdx.x * blockDim.x + threadIdx.x;
    const int NW = TT * (DD/4);
    if (i >= NW) return;
    int c4 = i % (DD/4);
    int t  = i / (DD/4);
    int l  = t & (LL - 1);
    int c  = c4 * 4;

    const float* p = xz + (size_t)t * (2*DD) + c;
    float4 x0 = *(const float4*)p;
    float4 xm = (l > 0)      ? *(const float4*)(p - 2*DD) : make_float4(0,0,0,0);
    float4 xp = (l < LL - 1) ? *(const float4*)(p + 2*DD) : make_float4(0,0,0,0);

    float xmv[4] = {xm.x, xm.y, xm.z, xm.w};
    float x0v[4] = {x0.x, x0.y, x0.z, x0.w};
    float xpv[4] = {xp.x, xp.y, xp.z, xp.w};
    float out[4];
    #pragma unroll
    for (int j = 0; j < 4; j++) {
        int cc = c + j;
        float v = xmv[j]*w[cc*3+0] + x0v[j]*w[cc*3+1] + xpv[j]*w[cc*3+2] + bias[cc];
        out[j] = silu_f(v);
    }
    *(float4*)(xc + (size_t)t*DD + c) = make_float4(out[0], out[1], out[2], out[3]);
    ushort4 h, l4;
    split1h(out[0], h.x, l4.x); split1h(out[1], h.y, l4.y);
    split1h(out[2], h.z, l4.z); split1h(out[3], h.w, l4.w);
    size_t o = ((size_t)t*DD + c) >> 2;
    ((ushort4*)xch)[o] = h;
    ((ushort4*)xcl)[o] = l4;
}

// ---------------- selective scan + fused gated mix ------------------------
#define SCH 32
#define SNC (LL / SCH)
#define SCAN_SMEM ((24576 + 2048) * 4)

__global__ __launch_bounds__(128)
void scan_kernel(const float* __restrict__ xc, const float* __restrict__ dt,
                 const float* __restrict__ xdbl, const float* __restrict__ A_log,
                 const float* __restrict__ xz, const float* __restrict__ Dp,
                 __half* __restrict__ yh, __half* __restrict__ yl)
{
    extern __shared__ float sm[];
    float* sU  = sm;
    float* sDT = sm + 8192;
    float* sZ  = sm + 16384;
    float* sBC = sm + 24576;

    const int tid = threadIdx.x;
    const int c0  = blockIdx.x * 128;
    const int c   = c0 + tid;
    const int b   = blockIdx.y;

    float eps[SSTATE];
    #pragma unroll
    for (int s = 0; s < SSTATE; s++)
        eps[s] = (float)(s + 1) - expf(A_log[(size_t)c*SSTATE + s]);
    const float Dv = Dp[c];

    float h[SSTATE];
    #pragma unroll
    for (int s = 0; s < SSTATE; s++) h[s] = 0.0f;

    const float* xcrow = xc   + (size_t)b * LL * DD + c0;
    const float* dtrow = dt   + (size_t)b * LL * DD + c0;
    const float* zrow  = xz   + (size_t)b * LL * (2*DD) + DD + c0;
    const float* bcrow = xdbl + (size_t)b * LL * XPAD + RR;

    const uint32_t sb = smem_u32(sm);
    auto load_chunk = [&](int lc, int buf) {
        const int l0 = lc * SCH;
        #pragma unroll
        for (int k = 0; k < 8; k++) {
            int idx = k * 128 + tid;
            int r = idx >> 5, q = idx & 31;
            uint32_t so = (uint32_t)(((buf * SCH + r) * 128 + q * 4) * 4);
            cp_async16(sb + so,           xcrow + (size_t)(l0 + r) * DD     + q * 4);
            cp_async16(sb + 32768 + so,   dtrow + (size_t)(l0 + r) * DD     + q * 4);
            cp_async16(sb + 65536 + so,   zrow  + (size_t)(l0 + r) * (2*DD) + q * 4);
        }
        #pragma unroll
        for (int k = 0; k < 2; k++) {
            int idx = k * 128 + tid;
            int r = idx >> 3, q = idx & 7;
            uint32_t so = (uint32_t)(98304 + ((buf * SCH + r) * 32 + q * 4) * 4);
            cp_async16(sb + so, bcrow + (size_t)(l0 + r) * XPAD + q * 4);
        }
        asm volatile("cp.async.commit_group;" ::: "memory");
    };

    load_chunk(0, 0);

    for (int lc = 0; lc < SNC; lc++) {
        const int buf = lc & 1;
        if (lc + 1 < SNC) {
            load_chunk(lc + 1, 1 - buf);
            asm volatile("cp.async.wait_group 1;" ::: "memory");
        } else {
            asm volatile("cp.async.wait_group 0;" ::: "memory");
        }
        __syncthreads();

        #pragma unroll 4
        for (int ll = 0; ll < SCH; ll++) {
            const int l = lc * SCH + ll;
            const int ro = (buf * SCH + ll);
            float u   = sU [ro * 128 + tid];
            float dtv = sDT[ro * 128 + tid];
            float zv  = sZ [ro * 128 + tid];
            const float4* bc = (const float4*)&sBC[ro * 32];
            float4 q0 = bc[0], q1 = bc[1], q2 = bc[2], q3 = bc[3];
            float4 q4 = bc[4], q5 = bc[5], q6 = bc[6], q7 = bc[7];
            float Bv[SSTATE] = {q0.x,q0.y,q0.z,q0.w, q1.x,q1.y,q1.z,q1.w,
                                q2.x,q2.y,q2.z,q2.w, q3.x,q3.y,q3.z,q3.w};
            float Cv[SSTATE] = {q4.x,q4.y,q4.z,q4.w, q5.x,q5.y,q5.z,q5.w,
                                q6.x,q6.y,q6.z,q6.w, q7.x,q7.y,q7.z,q7.w};

            float p1  = __expf(-dtv);
            float p2  = p1*p1;
            float p4  = p2*p2;
            float p8  = p4*p4;
            float p16 = p8*p8;
            float du  = dtv * u;

            float y0 = 0.f, y1 = 0.f, y2 = 0.f, y3 = 0.f;
            #pragma unroll
            for (int s = 0; s < SSTATE; s++) {
                const int e = s + 1;
                float pw = 1.0f;
                if (e & 1)  pw *= p1;
                if (e & 2)  pw *= p2;
                if (e & 4)  pw *= p4;
                if (e & 8)  pw *= p8;
                if (e & 16) pw *= p16;
                float dA = pw * fmaf(eps[s], dtv, 1.0f);
                h[s] = fmaf(dA, h[s], du * Bv[s]);
                float t2 = h[s] * Cv[s];
                if      ((s & 3) == 0) y0 += t2;
                else if ((s & 3) == 1) y1 += t2;
                else if ((s & 3) == 2) y2 += t2;
                else                   y3 += t2;
            }
            float ys = (y0 + y1) + (y2 + y3);
            float o  = fmaf(u, Dv, ys) * silu_f(zv);
            unsigned short oh, ol;
            split1h(o, oh, ol);
            size_t oidx = (size_t)b * LL * DD + (size_t)l * DD + c;
            *(unsigned short*)(yh + oidx) = oh;
            *(unsigned short*)(yl + oidx) = ol;
        }
        __syncthreads();
    }
}

// ---------------- launch ---------------------------------------------------
extern "C" void kernel_launch(void* const* d_in, const int* in_sizes, int n_in,
                              void* d_out, int out_size)
{
    const float* x      = (const float*)d_in[0];
    const float* W_in   = (const float*)d_in[1];
    const float* conv_w = (const float*)d_in[2];
    const float* conv_b = (const float*)d_in[3];
    const float* W_x    = (const float*)d_in[4];
    const float* W_dt   = (const float*)d_in[5];
    const float* b_dt   = (const float*)d_in[6];
    const float* A_log  = (const float*)d_in[7];
    const float* D      = (const float*)d_in[8];
    const float* W_out  = (const float*)d_in[9];
    float* out = (float*)d_out;

    float *xz, *xc, *xdbl, *xpart, *dtb;
    __half *xh, *xl, *wih, *woh, *yh, *yl;
    __half *wdh, *wdl, *wxh, *wxl, *xch, *xcl, *dih, *dil;
    cudaGetSymbolAddress((void**)&xz,    g_xz);
    cudaGetSymbolAddress((void**)&xc,    g_xc);
    cudaGetSymbolAddress((void**)&xdbl,  g_xdbl);
    cudaGetSymbolAddress((void**)&xpart, g_xpart);
    cudaGetSymbolAddress((void**)&dtb,   g_dt);
    cudaGetSymbolAddress((void**)&xh,  g_xh);  cudaGetSymbolAddress((void**)&xl,  g_xl);
    cudaGetSymbolAddress((void**)&wih, g_wih);
    cudaGetSymbolAddress((void**)&woh, g_woh);
    cudaGetSymbolAddress((void**)&wdh, g_wdh); cudaGetSymbolAddress((void**)&wdl, g_wdl);
    cudaGetSymbolAddress((void**)&wxh, g_wxh); cudaGetSymbolAddress((void**)&wxl, g_wxl);
    cudaGetSymbolAddress((void**)&xch, g_xch); cudaGetSymbolAddress((void**)&xcl, g_xcl);
    cudaGetSymbolAddress((void**)&dih, g_dih); cudaGetSymbolAddress((void**)&dil, g_dil);
    cudaGetSymbolAddress((void**)&yh,  g_yh);  cudaGetSymbolAddress((void**)&yl,  g_yl);

    cudaFuncSetAttribute((const void*)mma_gemm128h<0,1>, cudaFuncAttributeMaxDynamicSharedMemorySize, H_SMEM1);
    cudaFuncSetAttribute((const void*)mma_gemm128h<0,2>, cudaFuncAttributeMaxDynamicSharedMemorySize, H_SMEM2);
    cudaFuncSetAttribute((const void*)mma_gemm128h<0,3>, cudaFuncAttributeMaxDynamicSharedMemorySize, H_SMEM3);
    cudaFuncSetAttribute((const void*)mma_gemm128h<1,3>, cudaFuncAttributeMaxDynamicSharedMemorySize, H_SMEM3);
    cudaFuncSetAttribute((const void*)scan_kernel,       cudaFuncAttributeMaxDynamicSharedMemorySize, SCAN_SMEM);

    // idx0: split x -> fp16 hi/lo
    split_h_kernel<<<(TT*HH/4 + 255)/256, 256>>>(x, xh, xl, TT*HH/4);
    // idx1: W_in^T -> fp16 hi (fast 64x64)
    trsplit_h64<<<dim3(2*DD/64, HH/64), 256>>>(W_in, wih, HH, 2*DD);
    // idx2: W_out^T -> fp16 hi
    trsplit_h64<<<dim3(HH/64, DD/64), 256>>>(W_out, woh, DD, HH);
    // idx3 (ncu capture slot): GEMM1 merged: xz = x @ W_in (2048 x 8192, K=2048)
    //   xp half (bn<4096) 2-pass; z half (bn>=4096) 1-pass via n1pass.
    mma_gemm128h<0,2><<<dim3(2*DD/128, TT/128), 256, H_SMEM2>>>(
        xh, xl, wih, nullptr, xz, TT, 2*DD, HH, HH, nullptr, DD);
    // idx4: W_dt^T -> fp16 hi+lo
    trsplit_h2_64<<<dim3(DD/64, RR/64), 256>>>(W_dt, wdh, wdl, RR, DD);
    // idx5: W_x^T -> fp16 hi+lo (padded; 32-wide for C=160)
    trsplit_h2_32<<<dim3(XDBL_N/32, DD/32), 256>>>(W_x, wxh, wxl, DD, XDBL_N);
    // idx6: conv + silu -> xc + fp16 split
    conv_silu_kernel<<<(TT*(DD/4) + 255)/256, 256>>>(xz, conv_w, conv_b, xc, xch, xcl);
    // idx7: x_dbl split-K (fp16 3-pass)
    mma_gemm128h<0,3><<<dim3(XPAD/128, TT/128, NSPLITK), 256, H_SMEM3>>>(
        xch, xcl, wxh, wxl, xpart, TT, XPAD, DD, DD/NSPLITK, nullptr, XPAD);
    // idx8: reduce + dt_in split
    xdbl_reduce_kernel<<<(TT*(XPAD/4) + 255)/256, 256>>>(xpart, xdbl, dih, dil);
    // idx9: dt GEMM + softplus (fp16 3-pass, K=128)
    mma_gemm128h<1,3><<<dim3(DD/128, TT/128), 256, H_SMEM3>>>(
        dih, dil, wdh, wdl, dtb, TT, DD, RR, RR, b_dt, DD);
    // idx10: scan + fused mix -> yh/yl
    scan_kernel<<<dim3(DD/128, BBATCH), 128, SCAN_SMEM>>>(
        xc, dtb, xdbl, A_log, xz, D, yh, yl);
    // idx11: out = y @ W_out  (2048 x 2048, K=4096), 1-pass fp16
    mma_gemm128h<0,1><<<dim3(HH/128, TT/128), 256, H_SMEM1>>>(
        yh, nullptr, woh, nullptr, out, TT, HH, DD, DD, nullptr, 0);
}